// round 3
// baseline (speedup 1.0000x reference)
#include <cuda_runtime.h>
#include <cuda_bf16.h>

#define N_NODES 10000
#define N_E     640000
#define IN_DIM  128
#define HID_DIM 256
#define OUT_DIM 128

// ---------------- scratch (device globals; no allocation allowed) ----------------
__device__ int   g_deg[N_NODES];
__device__ float g_invdeg[N_NODES];
__device__ int   g_off[N_NODES + 1];
__device__ int   g_cursor[N_NODES];
__device__ int   g_csr[N_E];
__device__ float g_agg[N_NODES * 128];   // reused: agg1 (layer1) then agg2 (layer2)
__device__ float g_h[N_NODES * HID_DIM]; // relu(layer1) output
__device__ float g_p[N_NODES * 128];     // h @ W2_l (aggregated afterwards)

// ---------------- CSR build ----------------
__global__ void zero_deg_kernel() {
    int i = blockIdx.x * 256 + threadIdx.x;
    if (i < N_NODES) g_deg[i] = 0;
}

__global__ void hist_kernel(const int* __restrict__ ei) {
    int e = blockIdx.x * 256 + threadIdx.x;
    if (e < N_E) atomicAdd(&g_deg[ei[N_E + e]], 1);
}

// Single-block exclusive scan over 10000 degrees (1024 threads, 10 elems/thread).
__global__ void scan_kernel() {
    __shared__ int sh[1024];
    const int CH = 10;
    int tid = threadIdx.x;
    int base = tid * CH;
    int loc[CH];
    int s = 0;
#pragma unroll
    for (int i = 0; i < CH; i++) {
        int idx = base + i;
        int d = (idx < N_NODES) ? g_deg[idx] : 0;
        loc[i] = s;
        s += d;
    }
    sh[tid] = s;
    __syncthreads();
    for (int off = 1; off < 1024; off <<= 1) {
        int v = (tid >= off) ? sh[tid - off] : 0;
        __syncthreads();
        sh[tid] += v;
        __syncthreads();
    }
    int ex = (tid == 0) ? 0 : sh[tid - 1];
#pragma unroll
    for (int i = 0; i < CH; i++) {
        int idx = base + i;
        if (idx < N_NODES) {
            int o = ex + loc[i];
            g_off[idx] = o;
            g_cursor[idx] = o;
            g_invdeg[idx] = 1.0f / fmaxf((float)g_deg[idx], 1.0f);
        }
    }
    if (tid == 0) g_off[N_NODES] = sh[1023];
}

__global__ void scatter_kernel(const int* __restrict__ ei) {
    int e = blockIdx.x * 256 + threadIdx.x;
    if (e < N_E) {
        int dst = ei[N_E + e];
        int src = ei[e];
        int pos = atomicAdd(&g_cursor[dst], 1);
        g_csr[pos] = src;
    }
}

// ---------------- aggregation: one warp per node, 128-dim float4 lanes ----------------
// FROM_P=false: gather rows of x (kernel arg). FROM_P=true: gather rows of g_p.
// Writes the SUM into g_agg (division by degree folded into consumers).
template <bool FROM_P>
__global__ void aggregate_kernel(const float* __restrict__ xext) {
    const float* __restrict__ feat = FROM_P ? (const float*)g_p : xext;
    int warp = threadIdx.x >> 5;
    int lane = threadIdx.x & 31;
    int n = blockIdx.x * 8 + warp;
    if (n >= N_NODES) return;
    int beg = g_off[n];
    int end = g_off[n + 1];
    int c = lane * 4;
    float4 acc = make_float4(0.f, 0.f, 0.f, 0.f);
    int e = beg;
    for (; e + 1 < end; e += 2) {
        int s0 = g_csr[e];
        int s1 = g_csr[e + 1];
        float4 v0 = *(const float4*)&feat[(size_t)s0 * 128 + c];
        float4 v1 = *(const float4*)&feat[(size_t)s1 * 128 + c];
        acc.x += v0.x + v1.x;
        acc.y += v0.y + v1.y;
        acc.z += v0.z + v1.z;
        acc.w += v0.w + v1.w;
    }
    if (e < end) {
        int s0 = g_csr[e];
        float4 v0 = *(const float4*)&feat[(size_t)s0 * 128 + c];
        acc.x += v0.x; acc.y += v0.y; acc.z += v0.z; acc.w += v0.w;
    }
    *(float4*)&g_agg[(size_t)n * 128 + c] = acc;
}

// ---------------- GEMM1: h = relu([agg*inv | x] @ [W1_l; W1_r] + b1) ----------------
// M=10000, Nc=256, K=256(virtual). Tile 64x64x16, 256 threads, 4x4 per thread.
__global__ void gemm1_kernel(const float* __restrict__ x,
                             const float* __restrict__ W1l,
                             const float* __restrict__ W1r,
                             const float* __restrict__ b1) {
    __shared__ float As[16][68];
    __shared__ float Bs[16][64];
    int tid = threadIdx.x;
    int row0 = blockIdx.x * 64;
    int col0 = blockIdx.y * 64;
    int tx = tid & 15, ty = tid >> 4;

    int lm = tid >> 2;            // 0..63  A-tile row
    int lk4 = (tid & 3) * 4;      // 0,4,8,12
    int bk = tid >> 4;            // 0..15  B-tile row
    int bc4 = (tid & 15) * 4;     // 0..60  B-tile col

    int arow = row0 + lm;
    float inv = (arow < N_NODES) ? g_invdeg[arow] : 0.f;

    float acc[4][4];
#pragma unroll
    for (int i = 0; i < 4; i++)
#pragma unroll
        for (int j = 0; j < 4; j++) acc[i][j] = 0.f;

    for (int k0 = 0; k0 < 256; k0 += 16) {
        float4 av = make_float4(0.f, 0.f, 0.f, 0.f);
        if (arow < N_NODES) {
            int kk = k0 + lk4;
            if (kk < 128) {
                av = *(const float4*)&g_agg[(size_t)arow * 128 + kk];
                av.x *= inv; av.y *= inv; av.z *= inv; av.w *= inv;
            } else {
                av = *(const float4*)&x[(size_t)arow * 128 + (kk - 128)];
            }
        }
        As[lk4 + 0][lm] = av.x;
        As[lk4 + 1][lm] = av.y;
        As[lk4 + 2][lm] = av.z;
        As[lk4 + 3][lm] = av.w;
        {
            int kk = k0 + bk;
            const float* Bp = (kk < 128) ? &W1l[(size_t)kk * 256 + col0 + bc4]
                                         : &W1r[(size_t)(kk - 128) * 256 + col0 + bc4];
            *(float4*)&Bs[bk][bc4] = *(const float4*)Bp;
        }
        __syncthreads();
#pragma unroll
        for (int k = 0; k < 16; k++) {
            float4 a = *(const float4*)&As[k][ty * 4];
            float4 b = *(const float4*)&Bs[k][tx * 4];
            acc[0][0] += a.x * b.x; acc[0][1] += a.x * b.y; acc[0][2] += a.x * b.z; acc[0][3] += a.x * b.w;
            acc[1][0] += a.y * b.x; acc[1][1] += a.y * b.y; acc[1][2] += a.y * b.z; acc[1][3] += a.y * b.w;
            acc[2][0] += a.z * b.x; acc[2][1] += a.z * b.y; acc[2][2] += a.z * b.z; acc[2][3] += a.z * b.w;
            acc[3][0] += a.w * b.x; acc[3][1] += a.w * b.y; acc[3][2] += a.w * b.z; acc[3][3] += a.w * b.w;
        }
        __syncthreads();
    }
    int r0 = row0 + ty * 4, c0 = col0 + tx * 4;
#pragma unroll
    for (int i = 0; i < 4; i++) {
        int row = r0 + i;
        if (row < N_NODES) {
#pragma unroll
            for (int j = 0; j < 4; j++) {
                float v = acc[i][j] + b1[c0 + j];
                g_h[(size_t)row * 256 + c0 + j] = fmaxf(v, 0.f);
            }
        }
    }
}

// ---------------- GEMM2: [p | q+b2] = h @ [W2_l | W2_r]; q+b2 -> out ----------------
__global__ void gemm2_kernel(const float* __restrict__ W2l,
                             const float* __restrict__ W2r,
                             const float* __restrict__ b2,
                             float* __restrict__ out) {
    __shared__ float As[16][68];
    __shared__ float Bs[16][64];
    int tid = threadIdx.x;
    int row0 = blockIdx.x * 64;
    int col0 = blockIdx.y * 64;
    int tx = tid & 15, ty = tid >> 4;

    int lm = tid >> 2;
    int lk4 = (tid & 3) * 4;
    int bk = tid >> 4;
    int bc4 = (tid & 15) * 4;

    int arow = row0 + lm;

    float acc[4][4];
#pragma unroll
    for (int i = 0; i < 4; i++)
#pragma unroll
        for (int j = 0; j < 4; j++) acc[i][j] = 0.f;

    for (int k0 = 0; k0 < 256; k0 += 16) {
        float4 av = make_float4(0.f, 0.f, 0.f, 0.f);
        if (arow < N_NODES) {
            av = *(const float4*)&g_h[(size_t)arow * 256 + k0 + lk4];
        }
        As[lk4 + 0][lm] = av.x;
        As[lk4 + 1][lm] = av.y;
        As[lk4 + 2][lm] = av.z;
        As[lk4 + 3][lm] = av.w;
        {
            int kk = k0 + bk;
            int col = col0 + bc4;  // virtual column in [0,256)
            const float* Bp = (col < 128) ? &W2l[(size_t)kk * 128 + col]
                                          : &W2r[(size_t)kk * 128 + (col - 128)];
            *(float4*)&Bs[bk][bc4] = *(const float4*)Bp;
        }
        __syncthreads();
#pragma unroll
        for (int k = 0; k < 16; k++) {
            float4 a = *(const float4*)&As[k][ty * 4];
            float4 b = *(const float4*)&Bs[k][tx * 4];
            acc[0][0] += a.x * b.x; acc[0][1] += a.x * b.y; acc[0][2] += a.x * b.z; acc[0][3] += a.x * b.w;
            acc[1][0] += a.y * b.x; acc[1][1] += a.y * b.y; acc[1][2] += a.y * b.z; acc[1][3] += a.y * b.w;
            acc[2][0] += a.z * b.x; acc[2][1] += a.z * b.y; acc[2][2] += a.z * b.z; acc[2][3] += a.z * b.w;
            acc[3][0] += a.w * b.x; acc[3][1] += a.w * b.y; acc[3][2] += a.w * b.z; acc[3][3] += a.w * b.w;
        }
        __syncthreads();
    }
    int r0 = row0 + ty * 4, c0 = col0 + tx * 4;
#pragma unroll
    for (int i = 0; i < 4; i++) {
        int row = r0 + i;
        if (row < N_NODES) {
#pragma unroll
            for (int j = 0; j < 4; j++) {
                int c = c0 + j;
                float v = acc[i][j];
                if (c < 128) {
                    g_p[(size_t)row * 128 + c] = v;
                } else {
                    out[(size_t)row * 128 + (c - 128)] = v + b2[c - 128];
                }
            }
        }
    }
}

// ---------------- finalize: out += agg2 * invdeg ----------------
__global__ void finalize_kernel(float* __restrict__ out) {
    int i = blockIdx.x * 256 + threadIdx.x;
    if (i < N_NODES * 128) {
        int n = i >> 7;
        out[i] = out[i] + g_agg[i] * g_invdeg[n];
    }
}

// ---------------- launch ----------------
extern "C" void kernel_launch(void* const* d_in, const int* in_sizes, int n_in,
                              void* d_out, int out_size) {
    const float* x   = (const float*)d_in[0];
    const int*   ei  = (const int*)d_in[1];   // int64 in reference -> int32 in harness
    const float* W1l = (const float*)d_in[2];
    const float* b1  = (const float*)d_in[3];
    const float* W1r = (const float*)d_in[4];
    const float* W2l = (const float*)d_in[5];
    const float* b2  = (const float*)d_in[6];
    const float* W2r = (const float*)d_in[7];
    float* out = (float*)d_out;

    // CSR build
    zero_deg_kernel<<<(N_NODES + 255) / 256, 256>>>();
    hist_kernel<<<(N_E + 255) / 256, 256>>>(ei);
    scan_kernel<<<1, 1024>>>();
    scatter_kernel<<<(N_E + 255) / 256, 256>>>(ei);

    // Layer 1: aggregate x -> agg (sum), then h = relu([agg*inv | x] @ [W1_l;W1_r] + b1)
    aggregate_kernel<false><<<(N_NODES + 7) / 8, 256>>>(x);
    {
        dim3 grid((N_NODES + 63) / 64, 256 / 64);
        gemm1_kernel<<<grid, 256>>>(x, W1l, W1r, b1);
    }

    // Layer 2: p = h@W2_l, out = h@W2_r + b2; aggregate p -> agg; out += agg*inv
    {
        dim3 grid((N_NODES + 63) / 64, 256 / 64);
        gemm2_kernel<<<grid, 256>>>(W2l, W2r, b2, out);
    }
    aggregate_kernel<true><<<(N_NODES + 7) / 8, 256>>>(nullptr);
    finalize_kernel<<<(N_NODES * 128 + 255) / 256, 256>>>(out);
}

// round 7
// speedup vs baseline: 1.0828x; 1.0828x over previous
#include <cuda_runtime.h>
#include <cuda_bf16.h>

#define N_NODES 10000
#define N_E     640000
#define IN_DIM  128
#define HID_DIM 256
#define OUT_DIM 128

// ---------------- scratch (device globals; no allocation allowed) ----------------
__device__ int   g_deg[N_NODES];
__device__ float g_invdeg[N_NODES];
__device__ int   g_off[N_NODES + 1];
__device__ int   g_cursor[N_NODES];
__device__ int   g_csr[N_E];
__device__ float g_agg[N_NODES * 128];            // layer-1 neighbor sum (fp32)
__device__ float g_h[N_NODES * HID_DIM];          // relu(layer1) output (fp32)
__device__ __nv_bfloat16 g_xb[N_NODES * 128];     // bf16 copy of x (gather source)
__device__ __nv_bfloat16 g_pb[N_NODES * 128];     // bf16 h @ W2_l (gather source)

// ---------------- CSR build ----------------
__global__ void zero_deg_kernel() {
    int i = blockIdx.x * 256 + threadIdx.x;
    if (i < N_NODES) g_deg[i] = 0;
}

__global__ void hist_kernel(const int* __restrict__ ei) {
    int e = blockIdx.x * 256 + threadIdx.x;
    if (e < N_E) atomicAdd(&g_deg[ei[N_E + e]], 1);
}

// Single-block exclusive scan over 10000 degrees (1024 threads, 10 elems/thread).
__global__ void scan_kernel() {
    __shared__ int sh[1024];
    const int CH = 10;
    int tid = threadIdx.x;
    int base = tid * CH;
    int loc[CH];
    int s = 0;
#pragma unroll
    for (int i = 0; i < CH; i++) {
        int idx = base + i;
        int d = (idx < N_NODES) ? g_deg[idx] : 0;
        loc[i] = s;
        s += d;
    }
    sh[tid] = s;
    __syncthreads();
    for (int off = 1; off < 1024; off <<= 1) {
        int v = (tid >= off) ? sh[tid - off] : 0;
        __syncthreads();
        sh[tid] += v;
        __syncthreads();
    }
    int ex = (tid == 0) ? 0 : sh[tid - 1];
#pragma unroll
    for (int i = 0; i < CH; i++) {
        int idx = base + i;
        if (idx < N_NODES) {
            int o = ex + loc[i];
            g_off[idx] = o;
            g_cursor[idx] = o;
            g_invdeg[idx] = 1.0f / fmaxf((float)g_deg[idx], 1.0f);
        }
    }
    if (tid == 0) g_off[N_NODES] = sh[1023];
}

__global__ void scatter_kernel(const int* __restrict__ ei) {
    int e = blockIdx.x * 256 + threadIdx.x;
    if (e < N_E) {
        int dst = ei[N_E + e];
        int src = ei[e];
        int pos = atomicAdd(&g_cursor[dst], 1);
        g_csr[pos] = src;
    }
}

// ---------------- x -> bf16 copy ----------------
__global__ void convert_x_kernel(const float* __restrict__ x) {
    int i = blockIdx.x * 256 + threadIdx.x;   // one float4 -> 4 bf16 per thread
    if (i < N_NODES * 128 / 4) {
        float4 v = *(const float4*)&x[(size_t)i * 4];
        __nv_bfloat162 lo = __floats2bfloat162_rn(v.x, v.y);
        __nv_bfloat162 hi = __floats2bfloat162_rn(v.z, v.w);
        uint2 packed;
        packed.x = *(unsigned int*)&lo;
        packed.y = *(unsigned int*)&hi;
        *(uint2*)&g_xb[(size_t)i * 4] = packed;
    }
}

// ---------------- aggregation: one warp per node, 4 bf16 per lane ----------------
__device__ __forceinline__ void acc_bf16x4(float& a0, float& a1, float& a2, float& a3, uint2 v) {
    float2 lo = __bfloat1622float2(*(__nv_bfloat162*)&v.x);
    float2 hi = __bfloat1622float2(*(__nv_bfloat162*)&v.y);
    a0 += lo.x; a1 += lo.y; a2 += hi.x; a3 += hi.y;
}

// Layer 1: sum of bf16 x rows -> g_agg (fp32 sum; invdeg folded into gemm1)
__global__ void aggregate_x_kernel() {
    int warp = threadIdx.x >> 5;
    int lane = threadIdx.x & 31;
    int n = blockIdx.x * 8 + warp;
    if (n >= N_NODES) return;
    int beg = g_off[n];
    int end = g_off[n + 1];
    int c = lane * 4;
    float a0 = 0.f, a1 = 0.f, a2 = 0.f, a3 = 0.f;
    int e = beg;
    for (; e + 3 < end; e += 4) {
        int s0 = g_csr[e], s1 = g_csr[e + 1], s2 = g_csr[e + 2], s3 = g_csr[e + 3];
        uint2 v0 = *(const uint2*)&g_xb[(size_t)s0 * 128 + c];
        uint2 v1 = *(const uint2*)&g_xb[(size_t)s1 * 128 + c];
        uint2 v2 = *(const uint2*)&g_xb[(size_t)s2 * 128 + c];
        uint2 v3 = *(const uint2*)&g_xb[(size_t)s3 * 128 + c];
        acc_bf16x4(a0, a1, a2, a3, v0);
        acc_bf16x4(a0, a1, a2, a3, v1);
        acc_bf16x4(a0, a1, a2, a3, v2);
        acc_bf16x4(a0, a1, a2, a3, v3);
    }
    for (; e < end; e++) {
        int s0 = g_csr[e];
        uint2 v0 = *(const uint2*)&g_xb[(size_t)s0 * 128 + c];
        acc_bf16x4(a0, a1, a2, a3, v0);
    }
    *(float4*)&g_agg[(size_t)n * 128 + c] = make_float4(a0, a1, a2, a3);
}

// Layer 2: out[n] += mean of bf16 p rows (finalize fused)
__global__ void aggregate_p_kernel(float* __restrict__ out) {
    int warp = threadIdx.x >> 5;
    int lane = threadIdx.x & 31;
    int n = blockIdx.x * 8 + warp;
    if (n >= N_NODES) return;
    int beg = g_off[n];
    int end = g_off[n + 1];
    int c = lane * 4;
    float a0 = 0.f, a1 = 0.f, a2 = 0.f, a3 = 0.f;
    int e = beg;
    for (; e + 3 < end; e += 4) {
        int s0 = g_csr[e], s1 = g_csr[e + 1], s2 = g_csr[e + 2], s3 = g_csr[e + 3];
        uint2 v0 = *(const uint2*)&g_pb[(size_t)s0 * 128 + c];
        uint2 v1 = *(const uint2*)&g_pb[(size_t)s1 * 128 + c];
        uint2 v2 = *(const uint2*)&g_pb[(size_t)s2 * 128 + c];
        uint2 v3 = *(const uint2*)&g_pb[(size_t)s3 * 128 + c];
        acc_bf16x4(a0, a1, a2, a3, v0);
        acc_bf16x4(a0, a1, a2, a3, v1);
        acc_bf16x4(a0, a1, a2, a3, v2);
        acc_bf16x4(a0, a1, a2, a3, v3);
    }
    for (; e < end; e++) {
        int s0 = g_csr[e];
        uint2 v0 = *(const uint2*)&g_pb[(size_t)s0 * 128 + c];
        acc_bf16x4(a0, a1, a2, a3, v0);
    }
    float inv = g_invdeg[n];
    float4 o = *(float4*)&out[(size_t)n * 128 + c];
    o.x += a0 * inv; o.y += a1 * inv; o.z += a2 * inv; o.w += a3 * inv;
    *(float4*)&out[(size_t)n * 128 + c] = o;
}

// ---------------- GEMM1: h = relu([agg*inv | x] @ [W1_l; W1_r] + b1) ----------------
// M=10000, Nc=256, K=256(virtual). Tile 128x64x16, 256 threads, 8x4 per thread.
__global__ void gemm1_kernel(const float* __restrict__ x,
                             const float* __restrict__ W1l,
                             const float* __restrict__ W1r,
                             const float* __restrict__ b1) {
    __shared__ float As[16][136];   // [k][row], padded
    __shared__ float Bs[16][64];    // [k][col]
    int tid = threadIdx.x;
    int row0 = blockIdx.x * 128;
    int col0 = blockIdx.y * 64;
    int tx = tid & 15, ty = tid >> 4;

    int lm = tid >> 1;             // 0..127  A-tile row
    int lk8 = (tid & 1) * 8;       // 0 or 8  A-tile k base (loads k..k+3 and k+4..k+7)
    int bk = tid >> 4;             // 0..15   B-tile row (k)
    int bc4 = (tid & 15) * 4;      // B-tile col

    int arow = row0 + lm;
    bool rowok = (arow < N_NODES);
    float inv = rowok ? g_invdeg[arow] : 0.f;

    float acc[8][4];
#pragma unroll
    for (int i = 0; i < 8; i++)
#pragma unroll
        for (int j = 0; j < 4; j++) acc[i][j] = 0.f;

    for (int k0 = 0; k0 < 256; k0 += 16) {
        float4 av0 = make_float4(0.f, 0.f, 0.f, 0.f);
        float4 av1 = make_float4(0.f, 0.f, 0.f, 0.f);
        if (rowok) {
            if (k0 < 128) {
                int kk = k0 + lk8;
                av0 = *(const float4*)&g_agg[(size_t)arow * 128 + kk];
                av1 = *(const float4*)&g_agg[(size_t)arow * 128 + kk + 4];
                av0.x *= inv; av0.y *= inv; av0.z *= inv; av0.w *= inv;
                av1.x *= inv; av1.y *= inv; av1.z *= inv; av1.w *= inv;
            } else {
                int kk = k0 - 128 + lk8;
                av0 = *(const float4*)&x[(size_t)arow * 128 + kk];
                av1 = *(const float4*)&x[(size_t)arow * 128 + kk + 4];
            }
        }
        As[lk8 + 0][lm] = av0.x;
        As[lk8 + 1][lm] = av0.y;
        As[lk8 + 2][lm] = av0.z;
        As[lk8 + 3][lm] = av0.w;
        As[lk8 + 4][lm] = av1.x;
        As[lk8 + 5][lm] = av1.y;
        As[lk8 + 6][lm] = av1.z;
        As[lk8 + 7][lm] = av1.w;
        {
            int kk = k0 + bk;
            const float* Bp = (kk < 128) ? &W1l[(size_t)kk * 256 + col0 + bc4]
                                         : &W1r[(size_t)(kk - 128) * 256 + col0 + bc4];
            *(float4*)&Bs[bk][bc4] = *(const float4*)Bp;
        }
        __syncthreads();
#pragma unroll
        for (int k = 0; k < 16; k++) {
            float4 b = *(const float4*)&Bs[k][tx * 4];
            float4 a0 = *(const float4*)&As[k][ty * 8];
            float4 a1 = *(const float4*)&As[k][ty * 8 + 4];
            acc[0][0] += a0.x * b.x; acc[0][1] += a0.x * b.y; acc[0][2] += a0.x * b.z; acc[0][3] += a0.x * b.w;
            acc[1][0] += a0.y * b.x; acc[1][1] += a0.y * b.y; acc[1][2] += a0.y * b.z; acc[1][3] += a0.y * b.w;
            acc[2][0] += a0.z * b.x; acc[2][1] += a0.z * b.y; acc[2][2] += a0.z * b.z; acc[2][3] += a0.z * b.w;
            acc[3][0] += a0.w * b.x; acc[3][1] += a0.w * b.y; acc[3][2] += a0.w * b.z; acc[3][3] += a0.w * b.w;
            acc[4][0] += a1.x * b.x; acc[4][1] += a1.x * b.y; acc[4][2] += a1.x * b.z; acc[4][3] += a1.x * b.w;
            acc[5][0] += a1.y * b.x; acc[5][1] += a1.y * b.y; acc[5][2] += a1.y * b.z; acc[5][3] += a1.y * b.w;
            acc[6][0] += a1.z * b.x; acc[6][1] += a1.z * b.y; acc[6][2] += a1.z * b.z; acc[6][3] += a1.z * b.w;
            acc[7][0] += a1.w * b.x; acc[7][1] += a1.w * b.y; acc[7][2] += a1.w * b.z; acc[7][3] += a1.w * b.w;
        }
        __syncthreads();
    }
    int r0 = row0 + ty * 8, c0 = col0 + tx * 4;
    float4 bias = *(const float4*)&b1[c0];
#pragma unroll
    for (int i = 0; i < 8; i++) {
        int row = r0 + i;
        if (row < N_NODES) {
            float4 v;
            v.x = fmaxf(acc[i][0] + bias.x, 0.f);
            v.y = fmaxf(acc[i][1] + bias.y, 0.f);
            v.z = fmaxf(acc[i][2] + bias.z, 0.f);
            v.w = fmaxf(acc[i][3] + bias.w, 0.f);
            *(float4*)&g_h[(size_t)row * 256 + c0] = v;
        }
    }
}

// ---------------- GEMM2: [p(bf16) | out=q+b2] = h @ [W2_l | W2_r] ----------------
// Tile 128x64x16, 256 threads, 8x4 per thread. Virtual Nc = 256.
__global__ void gemm2_kernel(const float* __restrict__ W2l,
                             const float* __restrict__ W2r,
                             const float* __restrict__ b2,
                             float* __restrict__ out) {
    __shared__ float As[16][136];
    __shared__ float Bs[16][64];
    int tid = threadIdx.x;
    int row0 = blockIdx.x * 128;
    int col0 = blockIdx.y * 64;
    int tx = tid & 15, ty = tid >> 4;

    int lm = tid >> 1;
    int lk8 = (tid & 1) * 8;
    int bk = tid >> 4;
    int bc4 = (tid & 15) * 4;

    int arow = row0 + lm;
    bool rowok = (arow < N_NODES);

    float acc[8][4];
#pragma unroll
    for (int i = 0; i < 8; i++)
#pragma unroll
        for (int j = 0; j < 4; j++) acc[i][j] = 0.f;

    for (int k0 = 0; k0 < 256; k0 += 16) {
        float4 av0 = make_float4(0.f, 0.f, 0.f, 0.f);
        float4 av1 = make_float4(0.f, 0.f, 0.f, 0.f);
        if (rowok) {
            av0 = *(const float4*)&g_h[(size_t)arow * 256 + k0 + lk8];
            av1 = *(const float4*)&g_h[(size_t)arow * 256 + k0 + lk8 + 4];
        }
        As[lk8 + 0][lm] = av0.x;
        As[lk8 + 1][lm] = av0.y;
        As[lk8 + 2][lm] = av0.z;
        As[lk8 + 3][lm] = av0.w;
        As[lk8 + 4][lm] = av1.x;
        As[lk8 + 5][lm] = av1.y;
        As[lk8 + 6][lm] = av1.z;
        As[lk8 + 7][lm] = av1.w;
        {
            int kk = k0 + bk;
            int col = col0 + bc4;  // virtual column in [0,256)
            const float* Bp = (col < 128) ? &W2l[(size_t)kk * 128 + col]
                                          : &W2r[(size_t)kk * 128 + (col - 128)];
            *(float4*)&Bs[bk][bc4] = *(const float4*)Bp;
        }
        __syncthreads();
#pragma unroll
        for (int k = 0; k < 16; k++) {
            float4 b = *(const float4*)&Bs[k][tx * 4];
            float4 a0 = *(const float4*)&As[k][ty * 8];
            float4 a1 = *(const float4*)&As[k][ty * 8 + 4];
            acc[0][0] += a0.x * b.x; acc[0][1] += a0.x * b.y; acc[0][2] += a0.x * b.z; acc[0][3] += a0.x * b.w;
            acc[1][0] += a0.y * b.x; acc[1][1] += a0.y * b.y; acc[1][2] += a0.y * b.z; acc[1][3] += a0.y * b.w;
            acc[2][0] += a0.z * b.x; acc[2][1] += a0.z * b.y; acc[2][2] += a0.z * b.z; acc[2][3] += a0.z * b.w;
            acc[3][0] += a0.w * b.x; acc[3][1] += a0.w * b.y; acc[3][2] += a0.w * b.z; acc[3][3] += a0.w * b.w;
            acc[4][0] += a1.x * b.x; acc[4][1] += a1.x * b.y; acc[4][2] += a1.x * b.z; acc[4][3] += a1.x * b.w;
            acc[5][0] += a1.y * b.x; acc[5][1] += a1.y * b.y; acc[5][2] += a1.y * b.z; acc[5][3] += a1.y * b.w;
            acc[6][0] += a1.z * b.x; acc[6][1] += a1.z * b.y; acc[6][2] += a1.z * b.z; acc[6][3] += a1.z * b.w;
            acc[7][0] += a1.w * b.x; acc[7][1] += a1.w * b.y; acc[7][2] += a1.w * b.z; acc[7][3] += a1.w * b.w;
        }
        __syncthreads();
    }
    int r0 = row0 + ty * 8;
    int c0 = col0 + tx * 4;      // virtual column
    if (c0 < 128) {
        // p path -> bf16
#pragma unroll
        for (int i = 0; i < 8; i++) {
            int row = r0 + i;
            if (row < N_NODES) {
                __nv_bfloat162 lo = __floats2bfloat162_rn(acc[i][0], acc[i][1]);
                __nv_bfloat162 hi = __floats2bfloat162_rn(acc[i][2], acc[i][3]);
                uint2 packed;
                packed.x = *(unsigned int*)&lo;
                packed.y = *(unsigned int*)&hi;
                *(uint2*)&g_pb[(size_t)row * 128 + c0] = packed;
            }
        }
    } else {
        int c = c0 - 128;
        float4 bias = *(const float4*)&b2[c];
#pragma unroll
        for (int i = 0; i < 8; i++) {
            int row = r0 + i;
            if (row < N_NODES) {
                float4 v;
                v.x = acc[i][0] + bias.x;
                v.y = acc[i][1] + bias.y;
                v.z = acc[i][2] + bias.z;
                v.w = acc[i][3] + bias.w;
                *(float4*)&out[(size_t)row * 128 + c] = v;
            }
        }
    }
}

// ---------------- launch ----------------
extern "C" void kernel_launch(void* const* d_in, const int* in_sizes, int n_in,
                              void* d_out, int out_size) {
    const float* x   = (const float*)d_in[0];
    const int*   ei  = (const int*)d_in[1];   // int64 in reference -> int32 in harness
    const float* W1l = (const float*)d_in[2];
    const float* b1  = (const float*)d_in[3];
    const float* W1r = (const float*)d_in[4];
    const float* W2l = (const float*)d_in[5];
    const float* b2  = (const float*)d_in[6];
    const float* W2r = (const float*)d_in[7];
    float* out = (float*)d_out;

    // CSR build
    zero_deg_kernel<<<(N_NODES + 255) / 256, 256>>>();
    hist_kernel<<<(N_E + 255) / 256, 256>>>(ei);
    scan_kernel<<<1, 1024>>>();
    scatter_kernel<<<(N_E + 255) / 256, 256>>>(ei);

    // x -> bf16 gather copy
    convert_x_kernel<<<(N_NODES * 128 / 4 + 255) / 256, 256>>>(x);

    // Layer 1: aggregate bf16 x -> agg (fp32 sum), then h = relu([agg*inv | x] @ [W1_l;W1_r] + b1)
    aggregate_x_kernel<<<(N_NODES + 7) / 8, 256>>>();
    {
        dim3 grid((N_NODES + 127) / 128, 256 / 64);
        gemm1_kernel<<<grid, 256>>>(x, W1l, W1r, b1);
    }

    // Layer 2: p(bf16) = h@W2_l, out = h@W2_r + b2; then out += mean(p[neighbors])
    {
        dim3 grid((N_NODES + 127) / 128, 256 / 64);
        gemm2_kernel<<<grid, 256>>>(W2l, W2r, b2, out);
    }
    aggregate_p_kernel<<<(N_NODES + 7) / 8, 256>>>(out);
}

// round 12
// speedup vs baseline: 1.2726x; 1.1753x over previous
#include <cuda_runtime.h>
#include <cuda_bf16.h>
#include <cstdint>

#define N_NODES 10000
#define N_E     640000
#define IN_DIM  128
#define HID_DIM 256
#define OUT_DIM 128

// ---------------- scratch (device globals; no allocation allowed) ----------------
__device__ int   g_deg[N_NODES];
__device__ float g_invdeg[N_NODES];
__device__ int   g_off[N_NODES + 1];
__device__ int   g_cursor[N_NODES];
__device__ int   g_csr[N_E];
__device__ float g_agg[N_NODES * 128];            // layer-1 neighbor sum (fp32)
__device__ float g_h[N_NODES * HID_DIM];          // relu(layer1) output (fp32)
__device__ __nv_bfloat16 g_xb[N_NODES * 128];     // bf16 copy of x (gather source)
__device__ __nv_bfloat16 g_pb[N_NODES * 128];     // bf16 h @ W2_l (gather source)

// ---------------- CSR build ----------------
__global__ void zero_deg_kernel() {
    int i = blockIdx.x * 256 + threadIdx.x;
    if (i < N_NODES) g_deg[i] = 0;
}

__global__ void hist_kernel(const int* __restrict__ ei) {
    int e = blockIdx.x * 256 + threadIdx.x;
    if (e < N_E) atomicAdd(&g_deg[ei[N_E + e]], 1);
}

// Single-block exclusive scan over 10000 degrees (1024 threads, 10 elems/thread).
__global__ void scan_kernel() {
    __shared__ int sh[1024];
    const int CH = 10;
    int tid = threadIdx.x;
    int base = tid * CH;
    int loc[CH];
    int s = 0;
#pragma unroll
    for (int i = 0; i < CH; i++) {
        int idx = base + i;
        int d = (idx < N_NODES) ? g_deg[idx] : 0;
        loc[i] = s;
        s += d;
    }
    sh[tid] = s;
    __syncthreads();
    for (int off = 1; off < 1024; off <<= 1) {
        int v = (tid >= off) ? sh[tid - off] : 0;
        __syncthreads();
        sh[tid] += v;
        __syncthreads();
    }
    int ex = (tid == 0) ? 0 : sh[tid - 1];
#pragma unroll
    for (int i = 0; i < CH; i++) {
        int idx = base + i;
        if (idx < N_NODES) {
            int o = ex + loc[i];
            g_off[idx] = o;
            g_cursor[idx] = o;
            g_invdeg[idx] = 1.0f / fmaxf((float)g_deg[idx], 1.0f);
        }
    }
    if (tid == 0) g_off[N_NODES] = sh[1023];
}

__global__ void scatter_kernel(const int* __restrict__ ei) {
    int e = blockIdx.x * 256 + threadIdx.x;
    if (e < N_E) {
        int dst = ei[N_E + e];
        int src = ei[e];
        int pos = atomicAdd(&g_cursor[dst], 1);
        g_csr[pos] = src;
    }
}

// ---------------- x -> bf16 copy ----------------
__global__ void convert_x_kernel(const float* __restrict__ x) {
    int i = blockIdx.x * 256 + threadIdx.x;   // one float4 -> 4 bf16 per thread
    if (i < N_NODES * 128 / 4) {
        float4 v = *(const float4*)&x[(size_t)i * 4];
        __nv_bfloat162 lo = __floats2bfloat162_rn(v.x, v.y);
        __nv_bfloat162 hi = __floats2bfloat162_rn(v.z, v.w);
        uint2 packed;
        packed.x = *(unsigned int*)&lo;
        packed.y = *(unsigned int*)&hi;
        *(uint2*)&g_xb[(size_t)i * 4] = packed;
    }
}

// ---------------- aggregation: one warp per node, 4 bf16 per lane ----------------
__device__ __forceinline__ void acc_bf16x4(float& a0, float& a1, float& a2, float& a3, uint2 v) {
    float2 lo = __bfloat1622float2(*(__nv_bfloat162*)&v.x);
    float2 hi = __bfloat1622float2(*(__nv_bfloat162*)&v.y);
    a0 += lo.x; a1 += lo.y; a2 += hi.x; a3 += hi.y;
}

// Layer 1: sum of bf16 x rows -> g_agg (fp32 sum; invdeg folded into gemm1)
__global__ void aggregate_x_kernel() {
    int warp = threadIdx.x >> 5;
    int lane = threadIdx.x & 31;
    int n = blockIdx.x * 8 + warp;
    if (n >= N_NODES) return;
    int beg = g_off[n];
    int end = g_off[n + 1];
    int c = lane * 4;
    float a0 = 0.f, a1 = 0.f, a2 = 0.f, a3 = 0.f;
    int e = beg;
    for (; e + 3 < end; e += 4) {
        int s0 = g_csr[e], s1 = g_csr[e + 1], s2 = g_csr[e + 2], s3 = g_csr[e + 3];
        uint2 v0 = *(const uint2*)&g_xb[(size_t)s0 * 128 + c];
        uint2 v1 = *(const uint2*)&g_xb[(size_t)s1 * 128 + c];
        uint2 v2 = *(const uint2*)&g_xb[(size_t)s2 * 128 + c];
        uint2 v3 = *(const uint2*)&g_xb[(size_t)s3 * 128 + c];
        acc_bf16x4(a0, a1, a2, a3, v0);
        acc_bf16x4(a0, a1, a2, a3, v1);
        acc_bf16x4(a0, a1, a2, a3, v2);
        acc_bf16x4(a0, a1, a2, a3, v3);
    }
    for (; e < end; e++) {
        int s0 = g_csr[e];
        uint2 v0 = *(const uint2*)&g_xb[(size_t)s0 * 128 + c];
        acc_bf16x4(a0, a1, a2, a3, v0);
    }
    *(float4*)&g_agg[(size_t)n * 128 + c] = make_float4(a0, a1, a2, a3);
}

// Layer 2: out[n] += mean of bf16 p rows (finalize fused)
__global__ void aggregate_p_kernel(float* __restrict__ out) {
    int warp = threadIdx.x >> 5;
    int lane = threadIdx.x & 31;
    int n = blockIdx.x * 8 + warp;
    if (n >= N_NODES) return;
    int beg = g_off[n];
    int end = g_off[n + 1];
    int c = lane * 4;
    float a0 = 0.f, a1 = 0.f, a2 = 0.f, a3 = 0.f;
    int e = beg;
    for (; e + 3 < end; e += 4) {
        int s0 = g_csr[e], s1 = g_csr[e + 1], s2 = g_csr[e + 2], s3 = g_csr[e + 3];
        uint2 v0 = *(const uint2*)&g_pb[(size_t)s0 * 128 + c];
        uint2 v1 = *(const uint2*)&g_pb[(size_t)s1 * 128 + c];
        uint2 v2 = *(const uint2*)&g_pb[(size_t)s2 * 128 + c];
        uint2 v3 = *(const uint2*)&g_pb[(size_t)s3 * 128 + c];
        acc_bf16x4(a0, a1, a2, a3, v0);
        acc_bf16x4(a0, a1, a2, a3, v1);
        acc_bf16x4(a0, a1, a2, a3, v2);
        acc_bf16x4(a0, a1, a2, a3, v3);
    }
    for (; e < end; e++) {
        int s0 = g_csr[e];
        uint2 v0 = *(const uint2*)&g_pb[(size_t)s0 * 128 + c];
        acc_bf16x4(a0, a1, a2, a3, v0);
    }
    float inv = g_invdeg[n];
    float4 o = *(float4*)&out[(size_t)n * 128 + c];
    o.x += a0 * inv; o.y += a1 * inv; o.z += a2 * inv; o.w += a3 * inv;
    *(float4*)&out[(size_t)n * 128 + c] = o;
}

// ================= split-bf16 mma GEMMs =================
// fp32 A,B split into (hi, lo) bf16; C += Ahi*Bhi + Ahi*Blo + Alo*Bhi (fp32 acc).
// Block: 256 threads (8 warps as 4(m) x 2(n)). Block tile 128(M) x 64(N), K staged 32.
// Warp tile 32x32 = 2(m16) x 4(n8) mma tiles, mma.sync.m16n8k16.bf16.
// Smem stores packed bf16x2 k-pairs: A [m][kpair] stride 17, B transposed [n][kpair] stride 17.

__device__ __forceinline__ void mma_bf16(float* c, uint32_t a0, uint32_t a1, uint32_t a2, uint32_t a3,
                                         uint32_t b0, uint32_t b1) {
    asm volatile(
        "mma.sync.aligned.m16n8k16.row.col.f32.bf16.bf16.f32 "
        "{%0,%1,%2,%3}, {%4,%5,%6,%7}, {%8,%9}, {%0,%1,%2,%3};"
        : "+f"(c[0]), "+f"(c[1]), "+f"(c[2]), "+f"(c[3])
        : "r"(a0), "r"(a1), "r"(a2), "r"(a3), "r"(b0), "r"(b1));
}

__device__ __forceinline__ void split_bf16(float v, __nv_bfloat16& hi, __nv_bfloat16& lo) {
    hi = __float2bfloat16_rn(v);
    lo = __float2bfloat16_rn(v - __bfloat162float(hi));
}

#define APS 17   // A kpair stride (uint32 words)
#define BPS 17   // B kpair stride (uint32 words)

struct SmemGemm {
    uint32_t Ah[128 * APS];
    uint32_t Al[128 * APS];
    uint32_t Bh[64 * BPS];
    uint32_t Bl[64 * BPS];
};

// Shared A-store helper: 16 floats -> 8 hi/lo packed pairs at [lrow][lkh/2 ..]
__device__ __forceinline__ void store_A_split(SmemGemm* sm, int lrow, int lkh, const float* vals) {
    uint32_t* dh = &sm->Ah[lrow * APS + (lkh >> 1)];
    uint32_t* dl = &sm->Al[lrow * APS + (lkh >> 1)];
#pragma unroll
    for (int i = 0; i < 8; i++) {
        __nv_bfloat16 h0, l0, h1, l1;
        split_bf16(vals[2 * i], h0, l0);
        split_bf16(vals[2 * i + 1], h1, l1);
        __nv_bfloat162 ph; ph.x = h0; ph.y = h1;
        __nv_bfloat162 pl; pl.x = l0; pl.y = l1;
        dh[i] = *(uint32_t*)&ph;
        dl[i] = *(uint32_t*)&pl;
    }
}

// Shared B-store helper: 8 floats (one k, 8 consecutive n) -> transposed bf16 halves
__device__ __forceinline__ void store_B_split(SmemGemm* sm, int bk, int bn, const float* v) {
    __nv_bfloat16* BhH = (__nv_bfloat16*)sm->Bh;
    __nv_bfloat16* BlH = (__nv_bfloat16*)sm->Bl;
#pragma unroll
    for (int j = 0; j < 8; j++) {
        __nv_bfloat16 h, l;
        split_bf16(v[j], h, l);
        int idx = (bn + j) * (2 * BPS) + bk;   // half-index: n-stride 34 halves
        BhH[idx] = h;
        BlH[idx] = l;
    }
}

// Compute one K=32 chunk (2 ksteps of k16) for the 2x4 warp tile.
__device__ __forceinline__ void compute_chunk(SmemGemm* sm, int wm, int wn, int g, int tig,
                                              float acc[2][4][4]) {
#pragma unroll
    for (int ks = 0; ks < 2; ks++) {
        int kp = ks * 8;   // kpair base (k16 per step -> 8 pairs)
        uint32_t ah[2][4], al[2][4];
#pragma unroll
        for (int mt = 0; mt < 2; mt++) {
            const uint32_t* ph = &sm->Ah[(wm + mt * 16 + g) * APS + kp + tig];
            const uint32_t* pl = &sm->Al[(wm + mt * 16 + g) * APS + kp + tig];
            ah[mt][0] = ph[0];       al[mt][0] = pl[0];
            ah[mt][1] = ph[8 * APS]; al[mt][1] = pl[8 * APS];
            ah[mt][2] = ph[4];       al[mt][2] = pl[4];
            ah[mt][3] = ph[8 * APS + 4]; al[mt][3] = pl[8 * APS + 4];
        }
        uint32_t bh[4][2], bl[4][2];
#pragma unroll
        for (int nt = 0; nt < 4; nt++) {
            const uint32_t* ph = &sm->Bh[(wn + nt * 8 + g) * BPS + kp + tig];
            const uint32_t* pl = &sm->Bl[(wn + nt * 8 + g) * BPS + kp + tig];
            bh[nt][0] = ph[0]; bh[nt][1] = ph[4];
            bl[nt][0] = pl[0]; bl[nt][1] = pl[4];
        }
#pragma unroll
        for (int mt = 0; mt < 2; mt++)
#pragma unroll
            for (int nt = 0; nt < 4; nt++) {
                mma_bf16(acc[mt][nt], ah[mt][0], ah[mt][1], ah[mt][2], ah[mt][3],
                         bh[nt][0], bh[nt][1]);
                mma_bf16(acc[mt][nt], ah[mt][0], ah[mt][1], ah[mt][2], ah[mt][3],
                         bl[nt][0], bl[nt][1]);
                mma_bf16(acc[mt][nt], al[mt][0], al[mt][1], al[mt][2], al[mt][3],
                         bh[nt][0], bh[nt][1]);
            }
    }
}

// GEMM1: h = relu([agg*inv | x] @ [W1_l; W1_r] + b1).  K virtual = 256.
__global__ __launch_bounds__(256) void gemm1_kernel(const float* __restrict__ x,
                                                    const float* __restrict__ W1l,
                                                    const float* __restrict__ W1r,
                                                    const float* __restrict__ b1) {
    __shared__ SmemGemm sm;
    int tid = threadIdx.x;
    int row0 = blockIdx.x * 128;
    int col0 = blockIdx.y * 64;
    int wid = tid >> 5, lane = tid & 31;
    int g = lane >> 2, tig = lane & 3;
    int wm = (wid & 3) * 32;
    int wn = (wid >> 2) * 32;

    int lrow = tid >> 1;
    int lkh = (tid & 1) * 16;
    int arow = row0 + lrow;
    bool rowok = (arow < N_NODES);
    float inv = rowok ? g_invdeg[arow] : 0.f;

    int bk = tid >> 3;
    int bn = (tid & 7) * 8;

    float acc[2][4][4];
#pragma unroll
    for (int mt = 0; mt < 2; mt++)
#pragma unroll
        for (int nt = 0; nt < 4; nt++)
#pragma unroll
            for (int i = 0; i < 4; i++) acc[mt][nt][i] = 0.f;

    for (int k0 = 0; k0 < 256; k0 += 32) {
        // ---- A chunk
        {
            float vals[16];
            if (rowok) {
                if (k0 < 128) {
                    const float* src = &g_agg[(size_t)arow * 128 + k0 + lkh];
#pragma unroll
                    for (int i = 0; i < 4; i++) {
                        float4 v = *(const float4*)&src[i * 4];
                        vals[i * 4 + 0] = v.x * inv; vals[i * 4 + 1] = v.y * inv;
                        vals[i * 4 + 2] = v.z * inv; vals[i * 4 + 3] = v.w * inv;
                    }
                } else {
                    const float* src = &x[(size_t)arow * 128 + (k0 - 128) + lkh];
#pragma unroll
                    for (int i = 0; i < 4; i++) {
                        float4 v = *(const float4*)&src[i * 4];
                        vals[i * 4 + 0] = v.x; vals[i * 4 + 1] = v.y;
                        vals[i * 4 + 2] = v.z; vals[i * 4 + 3] = v.w;
                    }
                }
            } else {
#pragma unroll
                for (int i = 0; i < 16; i++) vals[i] = 0.f;
            }
            store_A_split(&sm, lrow, lkh, vals);
        }
        // ---- B chunk
        {
            int kk = k0 + bk;
            const float* Bp = (kk < 128) ? &W1l[(size_t)kk * 256 + col0 + bn]
                                         : &W1r[(size_t)(kk - 128) * 256 + col0 + bn];
            float v[8];
            float4 v0 = *(const float4*)&Bp[0];
            float4 v1 = *(const float4*)&Bp[4];
            v[0] = v0.x; v[1] = v0.y; v[2] = v0.z; v[3] = v0.w;
            v[4] = v1.x; v[5] = v1.y; v[6] = v1.z; v[7] = v1.w;
            store_B_split(&sm, bk, bn, v);
        }
        __syncthreads();
        compute_chunk(&sm, wm, wn, g, tig, acc);
        __syncthreads();
    }

    // ---- epilogue: relu(C + b1) -> g_h
#pragma unroll
    for (int nt = 0; nt < 4; nt++) {
        int col = col0 + wn + nt * 8 + tig * 2;
        float2 bb = *(const float2*)&b1[col];
#pragma unroll
        for (int mt = 0; mt < 2; mt++) {
            int r_lo = row0 + wm + mt * 16 + g;
            int r_hi = r_lo + 8;
            if (r_lo < N_NODES) {
                float2 v;
                v.x = fmaxf(acc[mt][nt][0] + bb.x, 0.f);
                v.y = fmaxf(acc[mt][nt][1] + bb.y, 0.f);
                *(float2*)&g_h[(size_t)r_lo * 256 + col] = v;
            }
            if (r_hi < N_NODES) {
                float2 v;
                v.x = fmaxf(acc[mt][nt][2] + bb.x, 0.f);
                v.y = fmaxf(acc[mt][nt][3] + bb.y, 0.f);
                *(float2*)&g_h[(size_t)r_hi * 256 + col] = v;
            }
        }
    }
}

// GEMM2: [p(bf16) | out=q+b2] = h @ [W2_l | W2_r].  K=256, virtual N=256.
__global__ __launch_bounds__(256) void gemm2_kernel(const float* __restrict__ W2l,
                                                    const float* __restrict__ W2r,
                                                    const float* __restrict__ b2,
                                                    float* __restrict__ out) {
    __shared__ SmemGemm sm;
    int tid = threadIdx.x;
    int row0 = blockIdx.x * 128;
    int col0 = blockIdx.y * 64;   // virtual col in [0,256)
    int wid = tid >> 5, lane = tid & 31;
    int g = lane >> 2, tig = lane & 3;
    int wm = (wid & 3) * 32;
    int wn = (wid >> 2) * 32;

    int lrow = tid >> 1;
    int lkh = (tid & 1) * 16;
    int arow = row0 + lrow;
    bool rowok = (arow < N_NODES);

    int bk = tid >> 3;
    int bn = (tid & 7) * 8;

    float acc[2][4][4];
#pragma unroll
    for (int mt = 0; mt < 2; mt++)
#pragma unroll
        for (int nt = 0; nt < 4; nt++)
#pragma unroll
            for (int i = 0; i < 4; i++) acc[mt][nt][i] = 0.f;

    for (int k0 = 0; k0 < 256; k0 += 32) {
        {
            float vals[16];
            if (rowok) {
                const float* src = &g_h[(size_t)arow * 256 + k0 + lkh];
#pragma unroll
                for (int i = 0; i < 4; i++) {
                    float4 v = *(const float4*)&src[i * 4];
                    vals[i * 4 + 0] = v.x; vals[i * 4 + 1] = v.y;
                    vals[i * 4 + 2] = v.z; vals[i * 4 + 3] = v.w;
                }
            } else {
#pragma unroll
                for (int i = 0; i < 16; i++) vals[i] = 0.f;
            }
            store_A_split(&sm, lrow, lkh, vals);
        }
        {
            int kk = k0 + bk;
            int col = col0 + bn;
            const float* Bp = (col < 128) ? &W2l[(size_t)kk * 128 + col]
                                          : &W2r[(size_t)kk * 128 + (col - 128)];
            float v[8];
            float4 v0 = *(const float4*)&Bp[0];
            float4 v1 = *(const float4*)&Bp[4];
            v[0] = v0.x; v[1] = v0.y; v[2] = v0.z; v[3] = v0.w;
            v[4] = v1.x; v[5] = v1.y; v[6] = v1.z; v[7] = v1.w;
            store_B_split(&sm, bk, bn, v);
        }
        __syncthreads();
        compute_chunk(&sm, wm, wn, g, tig, acc);
        __syncthreads();
    }

    // ---- epilogue: col<128 -> bf16 p;  col>=128 -> out = C + b2
#pragma unroll
    for (int nt = 0; nt < 4; nt++) {
        int col = col0 + wn + nt * 8 + tig * 2;   // virtual col
#pragma unroll
        for (int mt = 0; mt < 2; mt++) {
            int r_lo = row0 + wm + mt * 16 + g;
            int r_hi = r_lo + 8;
            if (col < 128) {
                if (r_lo < N_NODES) {
                    __nv_bfloat162 v = __floats2bfloat162_rn(acc[mt][nt][0], acc[mt][nt][1]);
                    *(__nv_bfloat162*)&g_pb[(size_t)r_lo * 128 + col] = v;
                }
                if (r_hi < N_NODES) {
                    __nv_bfloat162 v = __floats2bfloat162_rn(acc[mt][nt][2], acc[mt][nt][3]);
                    *(__nv_bfloat162*)&g_pb[(size_t)r_hi * 128 + col] = v;
                }
            } else {
                int c = col - 128;
                float2 bb = *(const float2*)&b2[c];
                if (r_lo < N_NODES) {
                    float2 v;
                    v.x = acc[mt][nt][0] + bb.x;
                    v.y = acc[mt][nt][1] + bb.y;
                    *(float2*)&out[(size_t)r_lo * 128 + c] = v;
                }
                if (r_hi < N_NODES) {
                    float2 v;
                    v.x = acc[mt][nt][2] + bb.x;
                    v.y = acc[mt][nt][3] + bb.y;
                    *(float2*)&out[(size_t)r_hi * 128 + c] = v;
                }
            }
        }
    }
}

// ---------------- launch ----------------
extern "C" void kernel_launch(void* const* d_in, const int* in_sizes, int n_in,
                              void* d_out, int out_size) {
    const float* x   = (const float*)d_in[0];
    const int*   ei  = (const int*)d_in[1];   // int64 in reference -> int32 in harness
    const float* W1l = (const float*)d_in[2];
    const float* b1  = (const float*)d_in[3];
    const float* W1r = (const float*)d_in[4];
    const float* W2l = (const float*)d_in[5];
    const float* b2  = (const float*)d_in[6];
    const float* W2r = (const float*)d_in[7];
    float* out = (float*)d_out;

    // CSR build
    zero_deg_kernel<<<(N_NODES + 255) / 256, 256>>>();
    hist_kernel<<<(N_E + 255) / 256, 256>>>(ei);
    scan_kernel<<<1, 1024>>>();
    scatter_kernel<<<(N_E + 255) / 256, 256>>>(ei);

    // x -> bf16 gather copy
    convert_x_kernel<<<(N_NODES * 128 / 4 + 255) / 256, 256>>>(x);

    // Layer 1: aggregate bf16 x -> agg (fp32 sum), then h = relu([agg*inv | x] @ [W1_l;W1_r] + b1)
    aggregate_x_kernel<<<(N_NODES + 7) / 8, 256>>>();
    {
        dim3 grid((N_NODES + 127) / 128, 4);
        gemm1_kernel<<<grid, 256>>>(x, W1l, W1r, b1);
    }

    // Layer 2: p(bf16) = h@W2_l, out = h@W2_r + b2; then out += mean(p[neighbors])
    {
        dim3 grid((N_NODES + 127) / 128, 4);
        gemm2_kernel<<<grid, 256>>>(W2l, W2r, b2, out);
    }
    aggregate_p_kernel<<<(N_NODES + 7) / 8, 256>>>(out);
}

// round 13
// speedup vs baseline: 1.3384x; 1.0517x over previous
#include <cuda_runtime.h>
#include <cuda_bf16.h>
#include <cstdint>

#define N_NODES 10000
#define N_E     640000
#define IN_DIM  128
#define HID_DIM 256
#define OUT_DIM 128

// ---------------- scratch (device globals; no allocation allowed) ----------------
__device__ int   g_deg[N_NODES];
__device__ float g_invdeg[N_NODES];
__device__ int   g_off[N_NODES + 1];
__device__ int   g_cursor[N_NODES];
__device__ int   g_csr[N_E];

// split-bf16 operand arrays (packed bf16x2 k-pairs, uint32 words)
__device__ __align__(16) uint32_t g_xbh[N_NODES * 64];   // x hi   [row][64 kpairs]
__device__ __align__(16) uint32_t g_xbl[N_NODES * 64];   // x lo
__device__ __align__(16) uint32_t g_aggh[N_NODES * 64];  // mean-agg hi
__device__ __align__(16) uint32_t g_aggl[N_NODES * 64];  // mean-agg lo
__device__ __align__(16) uint32_t g_hh[N_NODES * 128];   // h hi   [row][128 kpairs]
__device__ __align__(16) uint32_t g_hl[N_NODES * 128];   // h lo
__device__ __align__(16) uint32_t g_pb[N_NODES * 64];    // p bf16 (hi only, gather source)
// transposed split weights [n][kpair], 256 n x 128 kpairs each
__device__ __align__(16) uint32_t g_W1h[256 * 128];
__device__ __align__(16) uint32_t g_W1l[256 * 128];
__device__ __align__(16) uint32_t g_W2h[256 * 128];
__device__ __align__(16) uint32_t g_W2l[256 * 128];

// ---------------- CSR build ----------------
__global__ void zero_deg_kernel() {
    int i = blockIdx.x * 256 + threadIdx.x;
    if (i < N_NODES) g_deg[i] = 0;
}

__global__ void hist_kernel(const int* __restrict__ ei) {
    int e4 = blockIdx.x * 256 + threadIdx.x;
    if (e4 < N_E / 4) {
        int4 d = ((const int4*)(ei + N_E))[e4];
        atomicAdd(&g_deg[d.x], 1);
        atomicAdd(&g_deg[d.y], 1);
        atomicAdd(&g_deg[d.z], 1);
        atomicAdd(&g_deg[d.w], 1);
    }
}

// Single-block exclusive scan over 10000 degrees (1024 threads, 10 elems/thread).
__global__ void scan_kernel() {
    __shared__ int sh[1024];
    const int CH = 10;
    int tid = threadIdx.x;
    int base = tid * CH;
    int loc[CH];
    int s = 0;
#pragma unroll
    for (int i = 0; i < CH; i++) {
        int idx = base + i;
        int d = (idx < N_NODES) ? g_deg[idx] : 0;
        loc[i] = s;
        s += d;
    }
    sh[tid] = s;
    __syncthreads();
    for (int off = 1; off < 1024; off <<= 1) {
        int v = (tid >= off) ? sh[tid - off] : 0;
        __syncthreads();
        sh[tid] += v;
        __syncthreads();
    }
    int ex = (tid == 0) ? 0 : sh[tid - 1];
#pragma unroll
    for (int i = 0; i < CH; i++) {
        int idx = base + i;
        if (idx < N_NODES) {
            int o = ex + loc[i];
            g_off[idx] = o;
            g_cursor[idx] = o;
            g_invdeg[idx] = 1.0f / fmaxf((float)g_deg[idx], 1.0f);
        }
    }
    if (tid == 0) g_off[N_NODES] = sh[1023];
}

__global__ void scatter_kernel(const int* __restrict__ ei) {
    int e4 = blockIdx.x * 256 + threadIdx.x;
    if (e4 < N_E / 4) {
        int4 s = ((const int4*)ei)[e4];
        int4 d = ((const int4*)(ei + N_E))[e4];
        int p0 = atomicAdd(&g_cursor[d.x], 1); g_csr[p0] = s.x;
        int p1 = atomicAdd(&g_cursor[d.y], 1); g_csr[p1] = s.y;
        int p2 = atomicAdd(&g_cursor[d.z], 1); g_csr[p2] = s.z;
        int p3 = atomicAdd(&g_cursor[d.w], 1); g_csr[p3] = s.w;
    }
}

// ---------------- split helpers ----------------
__device__ __forceinline__ void split_bf16(float v, __nv_bfloat16& hi, __nv_bfloat16& lo) {
    hi = __float2bfloat16_rn(v);
    lo = __float2bfloat16_rn(v - __bfloat162float(hi));
}

__device__ __forceinline__ void split_pack2(float v0, float v1, uint32_t& ph, uint32_t& pl) {
    __nv_bfloat16 h0, l0, h1, l1;
    split_bf16(v0, h0, l0);
    split_bf16(v1, h1, l1);
    __nv_bfloat162 hh; hh.x = h0; hh.y = h1;
    __nv_bfloat162 ll; ll.x = l0; ll.y = l1;
    ph = *(uint32_t*)&hh;
    pl = *(uint32_t*)&ll;
}

// ---------------- x -> split bf16 ----------------
__global__ void prep_x_kernel(const float* __restrict__ x) {
    int i = blockIdx.x * 256 + threadIdx.x;   // one float4 -> 2 kpairs
    if (i < N_NODES * 128 / 4) {
        float4 v = *(const float4*)&x[(size_t)i * 4];
        uint32_t h0, l0, h1, l1;
        split_pack2(v.x, v.y, h0, l0);
        split_pack2(v.z, v.w, h1, l1);
        uint2 hv; hv.x = h0; hv.y = h1;
        uint2 lv; lv.x = l0; lv.y = l1;
        *(uint2*)&g_xbh[(size_t)i * 2] = hv;
        *(uint2*)&g_xbl[(size_t)i * 2] = lv;
    }
}

// ---------------- weights -> transposed split bf16 ----------------
// Wt1[n][kpair]: k<128 -> W1l[k][n], k>=128 -> W1r[k-128][n]
// Wt2[n][kpair]: n<128 -> W2l[k][n],  n>=128 -> W2r[k][n-128]
__global__ void prep_w_kernel(const float* __restrict__ W1lx, const float* __restrict__ W1rx,
                              const float* __restrict__ W2lx, const float* __restrict__ W2rx) {
    int i = blockIdx.x * 256 + threadIdx.x;   // 0 .. 2*256*128
    if (i >= 2 * 256 * 128) return;
    int mat = i >> 15;          // 0: W1, 1: W2
    int n = (i >> 7) & 255;
    int kp = i & 127;
    int k = kp * 2;
    float v0, v1;
    if (mat == 0) {
        if (k < 128) { v0 = W1lx[(size_t)k * 256 + n]; v1 = W1lx[(size_t)(k + 1) * 256 + n]; }
        else         { v0 = W1rx[(size_t)(k - 128) * 256 + n]; v1 = W1rx[(size_t)(k - 127) * 256 + n]; }
        uint32_t ph, pl;
        split_pack2(v0, v1, ph, pl);
        g_W1h[n * 128 + kp] = ph;
        g_W1l[n * 128 + kp] = pl;
    } else {
        if (n < 128) { v0 = W2lx[(size_t)k * 128 + n]; v1 = W2lx[(size_t)(k + 1) * 128 + n]; }
        else         { v0 = W2rx[(size_t)k * 128 + (n - 128)]; v1 = W2rx[(size_t)(k + 1) * 128 + (n - 128)]; }
        uint32_t ph, pl;
        split_pack2(v0, v1, ph, pl);
        g_W2h[n * 128 + kp] = ph;
        g_W2l[n * 128 + kp] = pl;
    }
}

// ---------------- aggregation: one warp per node, 4 bf16 per lane ----------------
__device__ __forceinline__ void acc_bf16x4(float& a0, float& a1, float& a2, float& a3, uint2 v) {
    float2 lo = __bfloat1622float2(*(__nv_bfloat162*)&v.x);
    float2 hi = __bfloat1622float2(*(__nv_bfloat162*)&v.y);
    a0 += lo.x; a1 += lo.y; a2 += hi.x; a3 += hi.y;
}

// Layer 1: mean of bf16 x rows -> split bf16 (g_aggh/g_aggl)
__global__ void aggregate_x_kernel() {
    int warp = threadIdx.x >> 5;
    int lane = threadIdx.x & 31;
    int n = blockIdx.x * 8 + warp;
    if (n >= N_NODES) return;
    int beg = g_off[n];
    int end = g_off[n + 1];
    int kp = lane * 2;            // 2 kpairs (4 bf16) per lane
    float a0 = 0.f, a1 = 0.f, a2 = 0.f, a3 = 0.f;
    int e = beg;
    for (; e + 3 < end; e += 4) {
        int s0 = g_csr[e], s1 = g_csr[e + 1], s2 = g_csr[e + 2], s3 = g_csr[e + 3];
        uint2 v0 = *(const uint2*)&g_xbh[(size_t)s0 * 64 + kp];
        uint2 v1 = *(const uint2*)&g_xbh[(size_t)s1 * 64 + kp];
        uint2 v2 = *(const uint2*)&g_xbh[(size_t)s2 * 64 + kp];
        uint2 v3 = *(const uint2*)&g_xbh[(size_t)s3 * 64 + kp];
        acc_bf16x4(a0, a1, a2, a3, v0);
        acc_bf16x4(a0, a1, a2, a3, v1);
        acc_bf16x4(a0, a1, a2, a3, v2);
        acc_bf16x4(a0, a1, a2, a3, v3);
    }
    for (; e < end; e++) {
        int s0 = g_csr[e];
        uint2 v0 = *(const uint2*)&g_xbh[(size_t)s0 * 64 + kp];
        acc_bf16x4(a0, a1, a2, a3, v0);
    }
    float inv = g_invdeg[n];
    uint32_t h0, l0, h1, l1;
    split_pack2(a0 * inv, a1 * inv, h0, l0);
    split_pack2(a2 * inv, a3 * inv, h1, l1);
    uint2 hv; hv.x = h0; hv.y = h1;
    uint2 lv; lv.x = l0; lv.y = l1;
    *(uint2*)&g_aggh[(size_t)n * 64 + kp] = hv;
    *(uint2*)&g_aggl[(size_t)n * 64 + kp] = lv;
}

// Layer 2: out[n] += mean of bf16 p rows (finalize fused)
__global__ void aggregate_p_kernel(float* __restrict__ out) {
    int warp = threadIdx.x >> 5;
    int lane = threadIdx.x & 31;
    int n = blockIdx.x * 8 + warp;
    if (n >= N_NODES) return;
    int beg = g_off[n];
    int end = g_off[n + 1];
    int kp = lane * 2;
    float a0 = 0.f, a1 = 0.f, a2 = 0.f, a3 = 0.f;
    int e = beg;
    for (; e + 3 < end; e += 4) {
        int s0 = g_csr[e], s1 = g_csr[e + 1], s2 = g_csr[e + 2], s3 = g_csr[e + 3];
        uint2 v0 = *(const uint2*)&g_pb[(size_t)s0 * 64 + kp];
        uint2 v1 = *(const uint2*)&g_pb[(size_t)s1 * 64 + kp];
        uint2 v2 = *(const uint2*)&g_pb[(size_t)s2 * 64 + kp];
        uint2 v3 = *(const uint2*)&g_pb[(size_t)s3 * 64 + kp];
        acc_bf16x4(a0, a1, a2, a3, v0);
        acc_bf16x4(a0, a1, a2, a3, v1);
        acc_bf16x4(a0, a1, a2, a3, v2);
        acc_bf16x4(a0, a1, a2, a3, v3);
    }
    for (; e < end; e++) {
        int s0 = g_csr[e];
        uint2 v0 = *(const uint2*)&g_pb[(size_t)s0 * 64 + kp];
        acc_bf16x4(a0, a1, a2, a3, v0);
    }
    float inv = g_invdeg[n];
    int c = lane * 4;
    float4 o = *(float4*)&out[(size_t)n * 128 + c];
    o.x += a0 * inv; o.y += a1 * inv; o.z += a2 * inv; o.w += a3 * inv;
    *(float4*)&out[(size_t)n * 128 + c] = o;
}

// ================= split-bf16 mma GEMMs (precomputed operands) =================
// C += Ahi*Bhi + Ahi*Blo + Alo*Bhi (fp32 acc), mma.sync.m16n8k16.bf16.
// Block: 256 threads (8 warps as 4(m) x 2(n)). Block tile 128(M) x 64(N), K staged 32.
// Smem: packed bf16x2 kpairs, row stride 20 words (conflict-free, uint4-aligned).

__device__ __forceinline__ void mma_bf16(float* c, uint32_t a0, uint32_t a1, uint32_t a2, uint32_t a3,
                                         uint32_t b0, uint32_t b1) {
    asm volatile(
        "mma.sync.aligned.m16n8k16.row.col.f32.bf16.bf16.f32 "
        "{%0,%1,%2,%3}, {%4,%5,%6,%7}, {%8,%9}, {%0,%1,%2,%3};"
        : "+f"(c[0]), "+f"(c[1]), "+f"(c[2]), "+f"(c[3])
        : "r"(a0), "r"(a1), "r"(a2), "r"(a3), "r"(b0), "r"(b1));
}

#define APS 20   // A kpair stride (uint32 words)
#define BPS 20   // B kpair stride (uint32 words)

struct SmemGemm {
    uint32_t Ah[128 * APS];
    uint32_t Al[128 * APS];
    uint32_t Bh[64 * BPS];
    uint32_t Bl[64 * BPS];
};

// Compute one K=32 chunk (2 ksteps of k16) for the 2x4 warp tile.
__device__ __forceinline__ void compute_chunk(SmemGemm* sm, int wm, int wn, int g, int tig,
                                              float acc[2][4][4]) {
#pragma unroll
    for (int ks = 0; ks < 2; ks++) {
        int kp = ks * 8;
        uint32_t ah[2][4], al[2][4];
#pragma unroll
        for (int mt = 0; mt < 2; mt++) {
            const uint32_t* ph = &sm->Ah[(wm + mt * 16 + g) * APS + kp + tig];
            const uint32_t* pl = &sm->Al[(wm + mt * 16 + g) * APS + kp + tig];
            ah[mt][0] = ph[0];       al[mt][0] = pl[0];
            ah[mt][1] = ph[8 * APS]; al[mt][1] = pl[8 * APS];
            ah[mt][2] = ph[4];       al[mt][2] = pl[4];
            ah[mt][3] = ph[8 * APS + 4]; al[mt][3] = pl[8 * APS + 4];
        }
        uint32_t bh[4][2], bl[4][2];
#pragma unroll
        for (int nt = 0; nt < 4; nt++) {
            const uint32_t* ph = &sm->Bh[(wn + nt * 8 + g) * BPS + kp + tig];
            const uint32_t* pl = &sm->Bl[(wn + nt * 8 + g) * BPS + kp + tig];
            bh[nt][0] = ph[0]; bh[nt][1] = ph[4];
            bl[nt][0] = pl[0]; bl[nt][1] = pl[4];
        }
#pragma unroll
        for (int mt = 0; mt < 2; mt++)
#pragma unroll
            for (int nt = 0; nt < 4; nt++) {
                mma_bf16(acc[mt][nt], ah[mt][0], ah[mt][1], ah[mt][2], ah[mt][3],
                         bh[nt][0], bh[nt][1]);
                mma_bf16(acc[mt][nt], ah[mt][0], ah[mt][1], ah[mt][2], ah[mt][3],
                         bl[nt][0], bl[nt][1]);
                mma_bf16(acc[mt][nt], al[mt][0], al[mt][1], al[mt][2], al[mt][3],
                         bh[nt][0], bh[nt][1]);
            }
    }
}

// Stage loaders: pure uint4 copies.
// A: 2 threads/row, 8 kpairs each.  B: 4 threads/n, 4 kpairs each.
__device__ __forceinline__ void load_A_stage(SmemGemm* sm, int lrow, int kq,
                                             const uint32_t* __restrict__ srch,
                                             const uint32_t* __restrict__ srcl, bool ok) {
    uint4 hv = make_uint4(0, 0, 0, 0), hv2 = hv, lv = hv, lv2 = hv;
    if (ok) {
        hv  = *(const uint4*)(srch + kq);
        hv2 = *(const uint4*)(srch + kq + 4);
        lv  = *(const uint4*)(srcl + kq);
        lv2 = *(const uint4*)(srcl + kq + 4);
    }
    *(uint4*)&sm->Ah[lrow * APS + kq]     = hv;
    *(uint4*)&sm->Ah[lrow * APS + kq + 4] = hv2;
    *(uint4*)&sm->Al[lrow * APS + kq]     = lv;
    *(uint4*)&sm->Al[lrow * APS + kq + 4] = lv2;
}

__device__ __forceinline__ void load_B_stage(SmemGemm* sm, int n, int kq4,
                                             const uint32_t* __restrict__ Wh,
                                             const uint32_t* __restrict__ Wl) {
    uint4 hv = *(const uint4*)(Wh + kq4);
    uint4 lv = *(const uint4*)(Wl + kq4);
    *(uint4*)&sm->Bh[n * BPS + kq4] = hv;
    *(uint4*)&sm->Bl[n * BPS + kq4] = lv;
}

// GEMM1: h = relu([agg_mean | x] @ [W1_l; W1_r] + b1) -> split bf16 g_hh/g_hl.
__global__ __launch_bounds__(256) void gemm1_kernel(const float* __restrict__ b1) {
    __shared__ SmemGemm sm;
    int tid = threadIdx.x;
    int row0 = blockIdx.x * 128;
    int col0 = blockIdx.y * 64;
    int wid = tid >> 5, lane = tid & 31;
    int g = lane >> 2, tig = lane & 3;
    int wm = (wid & 3) * 32;
    int wn = (wid >> 2) * 32;

    int lrow = tid >> 1;
    int kq = (tid & 1) * 8;
    int arow = row0 + lrow;
    bool rowok = (arow < N_NODES);

    int bn = tid >> 2;               // 0..63
    int kq4 = (tid & 3) * 4;         // 0,4,8,12

    float acc[2][4][4];
#pragma unroll
    for (int mt = 0; mt < 2; mt++)
#pragma unroll
        for (int nt = 0; nt < 4; nt++)
#pragma unroll
            for (int i = 0; i < 4; i++) acc[mt][nt][i] = 0.f;

    for (int k0 = 0; k0 < 256; k0 += 32) {
        int kb = k0 >> 1;    // kpair base
        const uint32_t *srch, *srcl;
        if (kb < 64) {
            srch = &g_aggh[(size_t)arow * 64 + kb];
            srcl = &g_aggl[(size_t)arow * 64 + kb];
        } else {
            srch = &g_xbh[(size_t)arow * 64 + (kb - 64)];
            srcl = &g_xbl[(size_t)arow * 64 + (kb - 64)];
        }
        load_A_stage(&sm, lrow, kq, srch, srcl, rowok);
        load_B_stage(&sm, bn, kq4, &g_W1h[(size_t)(col0 + bn) * 128 + kb],
                                    &g_W1l[(size_t)(col0 + bn) * 128 + kb]);
        __syncthreads();
        compute_chunk(&sm, wm, wn, g, tig, acc);
        __syncthreads();
    }

    // epilogue: relu(C + b1) -> split bf16 h
#pragma unroll
    for (int nt = 0; nt < 4; nt++) {
        int col = col0 + wn + nt * 8 + tig * 2;
        float2 bb = *(const float2*)&b1[col];
        int kpo = col >> 1;
#pragma unroll
        for (int mt = 0; mt < 2; mt++) {
            int r_lo = row0 + wm + mt * 16 + g;
            int r_hi = r_lo + 8;
            if (r_lo < N_NODES) {
                float v0 = fmaxf(acc[mt][nt][0] + bb.x, 0.f);
                float v1 = fmaxf(acc[mt][nt][1] + bb.y, 0.f);
                uint32_t ph, pl;
                split_pack2(v0, v1, ph, pl);
                g_hh[(size_t)r_lo * 128 + kpo] = ph;
                g_hl[(size_t)r_lo * 128 + kpo] = pl;
            }
            if (r_hi < N_NODES) {
                float v0 = fmaxf(acc[mt][nt][2] + bb.x, 0.f);
                float v1 = fmaxf(acc[mt][nt][3] + bb.y, 0.f);
                uint32_t ph, pl;
                split_pack2(v0, v1, ph, pl);
                g_hh[(size_t)r_hi * 128 + kpo] = ph;
                g_hl[(size_t)r_hi * 128 + kpo] = pl;
            }
        }
    }
}

// GEMM2: [p(bf16) | out=q+b2] = h @ [W2_l | W2_r].  K=256, virtual N=256.
__global__ __launch_bounds__(256) void gemm2_kernel(const float* __restrict__ b2,
                                                    float* __restrict__ out) {
    __shared__ SmemGemm sm;
    int tid = threadIdx.x;
    int row0 = blockIdx.x * 128;
    int col0 = blockIdx.y * 64;   // virtual col in [0,256)
    int wid = tid >> 5, lane = tid & 31;
    int g = lane >> 2, tig = lane & 3;
    int wm = (wid & 3) * 32;
    int wn = (wid >> 2) * 32;

    int lrow = tid >> 1;
    int kq = (tid & 1) * 8;
    int arow = row0 + lrow;
    bool rowok = (arow < N_NODES);

    int bn = tid >> 2;
    int kq4 = (tid & 3) * 4;

    float acc[2][4][4];
#pragma unroll
    for (int mt = 0; mt < 2; mt++)
#pragma unroll
        for (int nt = 0; nt < 4; nt++)
#pragma unroll
            for (int i = 0; i < 4; i++) acc[mt][nt][i] = 0.f;

    for (int k0 = 0; k0 < 256; k0 += 32) {
        int kb = k0 >> 1;
        load_A_stage(&sm, lrow, kq, &g_hh[(size_t)arow * 128 + kb],
                                    &g_hl[(size_t)arow * 128 + kb], rowok);
        load_B_stage(&sm, bn, kq4, &g_W2h[(size_t)(col0 + bn) * 128 + kb],
                                    &g_W2l[(size_t)(col0 + bn) * 128 + kb]);
        __syncthreads();
        compute_chunk(&sm, wm, wn, g, tig, acc);
        __syncthreads();
    }

    // epilogue: col<128 -> bf16 p;  col>=128 -> out = C + b2
#pragma unroll
    for (int nt = 0; nt < 4; nt++) {
        int col = col0 + wn + nt * 8 + tig * 2;   // virtual col
#pragma unroll
        for (int mt = 0; mt < 2; mt++) {
            int r_lo = row0 + wm + mt * 16 + g;
            int r_hi = r_lo + 8;
            if (col < 128) {
                int kpo = col >> 1;
                if (r_lo < N_NODES) {
                    __nv_bfloat162 v = __floats2bfloat162_rn(acc[mt][nt][0], acc[mt][nt][1]);
                    g_pb[(size_t)r_lo * 64 + kpo] = *(uint32_t*)&v;
                }
                if (r_hi < N_NODES) {
                    __nv_bfloat162 v = __floats2bfloat162_rn(acc[mt][nt][2], acc[mt][nt][3]);
                    g_pb[(size_t)r_hi * 64 + kpo] = *(uint32_t*)&v;
                }
            } else {
                int c = col - 128;
                float2 bb = *(const float2*)&b2[c];
                if (r_lo < N_NODES) {
                    float2 v;
                    v.x = acc[mt][nt][0] + bb.x;
                    v.y = acc[mt][nt][1] + bb.y;
                    *(float2*)&out[(size_t)r_lo * 128 + c] = v;
                }
                if (r_hi < N_NODES) {
                    float2 v;
                    v.x = acc[mt][nt][2] + bb.x;
                    v.y = acc[mt][nt][3] + bb.y;
                    *(float2*)&out[(size_t)r_hi * 128 + c] = v;
                }
            }
        }
    }
}

// ---------------- launch ----------------
extern "C" void kernel_launch(void* const* d_in, const int* in_sizes, int n_in,
                              void* d_out, int out_size) {
    const float* x   = (const float*)d_in[0];
    const int*   ei  = (const int*)d_in[1];   // int64 in reference -> int32 in harness
    const float* W1l = (const float*)d_in[2];
    const float* b1  = (const float*)d_in[3];
    const float* W1r = (const float*)d_in[4];
    const float* W2l = (const float*)d_in[5];
    const float* b2  = (const float*)d_in[6];
    const float* W2r = (const float*)d_in[7];
    float* out = (float*)d_out;

    // CSR build
    zero_deg_kernel<<<(N_NODES + 255) / 256, 256>>>();
    hist_kernel<<<(N_E / 4 + 255) / 256, 256>>>(ei);
    scan_kernel<<<1, 1024>>>();
    scatter_kernel<<<(N_E / 4 + 255) / 256, 256>>>(ei);

    // operand prep (split bf16)
    prep_x_kernel<<<(N_NODES * 128 / 4 + 255) / 256, 256>>>(x);
    prep_w_kernel<<<(2 * 256 * 128 + 255) / 256, 256>>>(W1l, W1r, W2l, W2r);

    // Layer 1
    aggregate_x_kernel<<<(N_NODES + 7) / 8, 256>>>();
    {
        dim3 grid((N_NODES + 127) / 128, 4);
        gemm1_kernel<<<grid, 256>>>(b1);
    }

    // Layer 2
    {
        dim3 grid((N_NODES + 127) / 128, 4);
        gemm2_kernel<<<grid, 256>>>(b2, out);
    }
    aggregate_p_kernel<<<(N_NODES + 7) / 8, 256>>>(out);
}

// round 14
// speedup vs baseline: 1.3885x; 1.0374x over previous
#include <cuda_runtime.h>
#include <cuda_bf16.h>
#include <cstdint>

#define N_NODES 10000
#define N_E     640000
#define IN_DIM  128
#define HID_DIM 256
#define OUT_DIM 128

// ---------------- scratch (device globals; no allocation allowed) ----------------
__device__ int   g_deg[N_NODES];
__device__ float g_invdeg[N_NODES];
__device__ int   g_off[N_NODES + 1];
__device__ int   g_cursor[N_NODES];
__device__ int   g_csr[N_E];

// split-bf16 operand arrays (packed bf16x2 k-pairs, uint32 words)
__device__ __align__(16) uint32_t g_xbh[N_NODES * 64];   // x hi   [row][64 kpairs]
__device__ __align__(16) uint32_t g_xbl[N_NODES * 64];   // x lo
__device__ __align__(16) uint32_t g_aggh[N_NODES * 64];  // mean-agg hi
__device__ __align__(16) uint32_t g_aggl[N_NODES * 64];  // mean-agg lo
__device__ __align__(16) uint32_t g_hh[N_NODES * 128];   // h hi   [row][128 kpairs]
__device__ __align__(16) uint32_t g_hl[N_NODES * 128];   // h lo
__device__ __align__(16) uint32_t g_pb[N_NODES * 64];    // p bf16 (hi only, gather source)
// transposed split weights [n][kpair], 256 n x 128 kpairs each
__device__ __align__(16) uint32_t g_W1h[256 * 128];
__device__ __align__(16) uint32_t g_W1l[256 * 128];
__device__ __align__(16) uint32_t g_W2h[256 * 128];
__device__ __align__(16) uint32_t g_W2l[256 * 128];

// ---------------- split helpers ----------------
__device__ __forceinline__ void split_bf16(float v, __nv_bfloat16& hi, __nv_bfloat16& lo) {
    hi = __float2bfloat16_rn(v);
    lo = __float2bfloat16_rn(v - __bfloat162float(hi));
}

__device__ __forceinline__ void split_pack2(float v0, float v1, uint32_t& ph, uint32_t& pl) {
    __nv_bfloat16 h0, l0, h1, l1;
    split_bf16(v0, h0, l0);
    split_bf16(v1, h1, l1);
    __nv_bfloat162 hh; hh.x = h0; hh.y = h1;
    __nv_bfloat162 ll; ll.x = l0; ll.y = l1;
    ph = *(uint32_t*)&hh;
    pl = *(uint32_t*)&ll;
}

// ---------------- fused init: zero_deg + prep_x + prep_w ----------------
__global__ void init_kernel(const float* __restrict__ x,
                            const float* __restrict__ W1lx, const float* __restrict__ W1rx,
                            const float* __restrict__ W2lx, const float* __restrict__ W2rx) {
    int i = blockIdx.x * 256 + threadIdx.x;
    if (i < N_NODES) g_deg[i] = 0;
    // prep x: one float4 -> 2 kpairs
    if (i < N_NODES * 128 / 4) {
        float4 v = *(const float4*)&x[(size_t)i * 4];
        uint32_t h0, l0, h1, l1;
        split_pack2(v.x, v.y, h0, l0);
        split_pack2(v.z, v.w, h1, l1);
        uint2 hv; hv.x = h0; hv.y = h1;
        uint2 lv; lv.x = l0; lv.y = l1;
        *(uint2*)&g_xbh[(size_t)i * 2] = hv;
        *(uint2*)&g_xbl[(size_t)i * 2] = lv;
    }
    // prep weights (transposed split)
    if (i < 2 * 256 * 128) {
        int mat = i >> 15;          // 0: W1, 1: W2
        int n = (i >> 7) & 255;
        int kp = i & 127;
        int k = kp * 2;
        float v0, v1;
        if (mat == 0) {
            if (k < 128) { v0 = W1lx[(size_t)k * 256 + n]; v1 = W1lx[(size_t)(k + 1) * 256 + n]; }
            else         { v0 = W1rx[(size_t)(k - 128) * 256 + n]; v1 = W1rx[(size_t)(k - 127) * 256 + n]; }
            uint32_t ph, pl;
            split_pack2(v0, v1, ph, pl);
            g_W1h[n * 128 + kp] = ph;
            g_W1l[n * 128 + kp] = pl;
        } else {
            if (n < 128) { v0 = W2lx[(size_t)k * 128 + n]; v1 = W2lx[(size_t)(k + 1) * 128 + n]; }
            else         { v0 = W2rx[(size_t)k * 128 + (n - 128)]; v1 = W2rx[(size_t)(k + 1) * 128 + (n - 128)]; }
            uint32_t ph, pl;
            split_pack2(v0, v1, ph, pl);
            g_W2h[n * 128 + kp] = ph;
            g_W2l[n * 128 + kp] = pl;
        }
    }
}

// ---------------- CSR build ----------------
__global__ void hist_kernel(const int* __restrict__ ei) {
    int e4 = blockIdx.x * 256 + threadIdx.x;
    if (e4 < N_E / 4) {
        int4 d = ((const int4*)(ei + N_E))[e4];
        atomicAdd(&g_deg[d.x], 1);
        atomicAdd(&g_deg[d.y], 1);
        atomicAdd(&g_deg[d.z], 1);
        atomicAdd(&g_deg[d.w], 1);
    }
}

// Single-block exclusive scan over 10000 degrees (1024 threads, 10 elems/thread).
__global__ void scan_kernel() {
    __shared__ int sh[1024];
    const int CH = 10;
    int tid = threadIdx.x;
    int base = tid * CH;
    int loc[CH];
    int s = 0;
#pragma unroll
    for (int i = 0; i < CH; i++) {
        int idx = base + i;
        int d = (idx < N_NODES) ? g_deg[idx] : 0;
        loc[i] = s;
        s += d;
    }
    sh[tid] = s;
    __syncthreads();
    for (int off = 1; off < 1024; off <<= 1) {
        int v = (tid >= off) ? sh[tid - off] : 0;
        __syncthreads();
        sh[tid] += v;
        __syncthreads();
    }
    int ex = (tid == 0) ? 0 : sh[tid - 1];
#pragma unroll
    for (int i = 0; i < CH; i++) {
        int idx = base + i;
        if (idx < N_NODES) {
            int o = ex + loc[i];
            g_off[idx] = o;
            g_cursor[idx] = o;
            g_invdeg[idx] = 1.0f / fmaxf((float)g_deg[idx], 1.0f);
        }
    }
    if (tid == 0) g_off[N_NODES] = sh[1023];
}

__global__ void scatter_kernel(const int* __restrict__ ei) {
    int e4 = blockIdx.x * 256 + threadIdx.x;
    if (e4 < N_E / 4) {
        int4 s = ((const int4*)ei)[e4];
        int4 d = ((const int4*)(ei + N_E))[e4];
        int p0 = atomicAdd(&g_cursor[d.x], 1); g_csr[p0] = s.x;
        int p1 = atomicAdd(&g_cursor[d.y], 1); g_csr[p1] = s.y;
        int p2 = atomicAdd(&g_cursor[d.z], 1); g_csr[p2] = s.z;
        int p3 = atomicAdd(&g_cursor[d.w], 1); g_csr[p3] = s.w;
    }
}

// ---------------- aggregation: one warp per node, half-warp edge substreams ----------------
// Each 16-lane group covers the full 128-dim row (uint4 = 8 bf16 per lane) for its own
// edge substream; halves combined with shfl at the end.
__device__ __forceinline__ void acc8(float* a, uint4 v) {
    float2 p0 = __bfloat1622float2(*(__nv_bfloat162*)&v.x);
    float2 p1 = __bfloat1622float2(*(__nv_bfloat162*)&v.y);
    float2 p2 = __bfloat1622float2(*(__nv_bfloat162*)&v.z);
    float2 p3 = __bfloat1622float2(*(__nv_bfloat162*)&v.w);
    a[0] += p0.x; a[1] += p0.y; a[2] += p1.x; a[3] += p1.y;
    a[4] += p2.x; a[5] += p2.y; a[6] += p3.x; a[7] += p3.y;
}

// Layer 1: mean of bf16 x rows -> split bf16 (g_aggh/g_aggl)
__global__ void aggregate_x_kernel() {
    int warp = threadIdx.x >> 5;
    int lane = threadIdx.x & 31;
    int n = blockIdx.x * 8 + warp;
    if (n >= N_NODES) return;
    int h = lane >> 4;          // substream 0/1
    int lh = lane & 15;
    int kp = lh * 4;            // 4 kpairs = 8 bf16 dims per lane
    int beg = g_off[n];
    int end = g_off[n + 1];
    float a[8] = {0.f, 0.f, 0.f, 0.f, 0.f, 0.f, 0.f, 0.f};
    int e = beg + h;
    for (; e + 2 < end; e += 4) {
        int s0 = g_csr[e];
        int s1 = g_csr[e + 2];
        uint4 v0 = *(const uint4*)&g_xbh[(size_t)s0 * 64 + kp];
        uint4 v1 = *(const uint4*)&g_xbh[(size_t)s1 * 64 + kp];
        acc8(a, v0);
        acc8(a, v1);
    }
    if (e < end) {
        int s0 = g_csr[e];
        uint4 v0 = *(const uint4*)&g_xbh[(size_t)s0 * 64 + kp];
        acc8(a, v0);
    }
#pragma unroll
    for (int i = 0; i < 8; i++) a[i] += __shfl_down_sync(0xffffffffu, a[i], 16);
    if (h == 0) {
        float inv = g_invdeg[n];
        uint4 hv, lv;
        split_pack2(a[0] * inv, a[1] * inv, hv.x, lv.x);
        split_pack2(a[2] * inv, a[3] * inv, hv.y, lv.y);
        split_pack2(a[4] * inv, a[5] * inv, hv.z, lv.z);
        split_pack2(a[6] * inv, a[7] * inv, hv.w, lv.w);
        *(uint4*)&g_aggh[(size_t)n * 64 + kp] = hv;
        *(uint4*)&g_aggl[(size_t)n * 64 + kp] = lv;
    }
}

// Layer 2: out[n] += mean of bf16 p rows (finalize fused)
__global__ void aggregate_p_kernel(float* __restrict__ out) {
    int warp = threadIdx.x >> 5;
    int lane = threadIdx.x & 31;
    int n = blockIdx.x * 8 + warp;
    if (n >= N_NODES) return;
    int h = lane >> 4;
    int lh = lane & 15;
    int kp = lh * 4;
    int beg = g_off[n];
    int end = g_off[n + 1];
    float a[8] = {0.f, 0.f, 0.f, 0.f, 0.f, 0.f, 0.f, 0.f};
    int e = beg + h;
    for (; e + 2 < end; e += 4) {
        int s0 = g_csr[e];
        int s1 = g_csr[e + 2];
        uint4 v0 = *(const uint4*)&g_pb[(size_t)s0 * 64 + kp];
        uint4 v1 = *(const uint4*)&g_pb[(size_t)s1 * 64 + kp];
        acc8(a, v0);
        acc8(a, v1);
    }
    if (e < end) {
        int s0 = g_csr[e];
        uint4 v0 = *(const uint4*)&g_pb[(size_t)s0 * 64 + kp];
        acc8(a, v0);
    }
#pragma unroll
    for (int i = 0; i < 8; i++) a[i] += __shfl_down_sync(0xffffffffu, a[i], 16);
    if (h == 0) {
        float inv = g_invdeg[n];
        int c = lh * 8;
        float4 o0 = *(float4*)&out[(size_t)n * 128 + c];
        float4 o1 = *(float4*)&out[(size_t)n * 128 + c + 4];
        o0.x += a[0] * inv; o0.y += a[1] * inv; o0.z += a[2] * inv; o0.w += a[3] * inv;
        o1.x += a[4] * inv; o1.y += a[5] * inv; o1.z += a[6] * inv; o1.w += a[7] * inv;
        *(float4*)&out[(size_t)n * 128 + c] = o0;
        *(float4*)&out[(size_t)n * 128 + c + 4] = o1;
    }
}

// ================= split-bf16 mma GEMMs (register-prefetch pipelined) =================
// C += Ahi*Bhi + Ahi*Blo + Alo*Bhi (fp32 acc), mma.sync.m16n8k16.bf16.
// Block: 256 threads (8 warps as 4(m) x 2(n)). Block tile 128(M) x 64(N), K staged 32.
// Smem: packed bf16x2 kpairs, row stride 20 words (conflict-free, uint4-aligned).
// Global loads for stage s+1 are issued right after stage s's smem store, so their
// latency overlaps stage-s compute.

__device__ __forceinline__ void mma_bf16(float* c, uint32_t a0, uint32_t a1, uint32_t a2, uint32_t a3,
                                         uint32_t b0, uint32_t b1) {
    asm volatile(
        "mma.sync.aligned.m16n8k16.row.col.f32.bf16.bf16.f32 "
        "{%0,%1,%2,%3}, {%4,%5,%6,%7}, {%8,%9}, {%0,%1,%2,%3};"
        : "+f"(c[0]), "+f"(c[1]), "+f"(c[2]), "+f"(c[3])
        : "r"(a0), "r"(a1), "r"(a2), "r"(a3), "r"(b0), "r"(b1));
}

#define APS 20   // A kpair stride (uint32 words)
#define BPS 20   // B kpair stride (uint32 words)

struct SmemGemm {
    uint32_t Ah[128 * APS];
    uint32_t Al[128 * APS];
    uint32_t Bh[64 * BPS];
    uint32_t Bl[64 * BPS];
};

struct StageRegs {
    uint4 ah0, ah1, al0, al1;   // A: 8 kpairs hi + lo
    uint4 bh, bl;               // B: 4 kpairs hi + lo
};

// Compute one K=32 chunk (2 ksteps of k16) for the 2x4 warp tile.
__device__ __forceinline__ void compute_chunk(SmemGemm* sm, int wm, int wn, int g, int tig,
                                              float acc[2][4][4]) {
#pragma unroll
    for (int ks = 0; ks < 2; ks++) {
        int kp = ks * 8;
        uint32_t ah[2][4], al[2][4];
#pragma unroll
        for (int mt = 0; mt < 2; mt++) {
            const uint32_t* ph = &sm->Ah[(wm + mt * 16 + g) * APS + kp + tig];
            const uint32_t* pl = &sm->Al[(wm + mt * 16 + g) * APS + kp + tig];
            ah[mt][0] = ph[0];       al[mt][0] = pl[0];
            ah[mt][1] = ph[8 * APS]; al[mt][1] = pl[8 * APS];
            ah[mt][2] = ph[4];       al[mt][2] = pl[4];
            ah[mt][3] = ph[8 * APS + 4]; al[mt][3] = pl[8 * APS + 4];
        }
        uint32_t bh[4][2], bl[4][2];
#pragma unroll
        for (int nt = 0; nt < 4; nt++) {
            const uint32_t* ph = &sm->Bh[(wn + nt * 8 + g) * BPS + kp + tig];
            const uint32_t* pl = &sm->Bl[(wn + nt * 8 + g) * BPS + kp + tig];
            bh[nt][0] = ph[0]; bh[nt][1] = ph[4];
            bl[nt][0] = pl[0]; bl[nt][1] = pl[4];
        }
#pragma unroll
        for (int mt = 0; mt < 2; mt++)
#pragma unroll
            for (int nt = 0; nt < 4; nt++) {
                mma_bf16(acc[mt][nt], ah[mt][0], ah[mt][1], ah[mt][2], ah[mt][3],
                         bh[nt][0], bh[nt][1]);
                mma_bf16(acc[mt][nt], ah[mt][0], ah[mt][1], ah[mt][2], ah[mt][3],
                         bl[nt][0], bl[nt][1]);
                mma_bf16(acc[mt][nt], al[mt][0], al[mt][1], al[mt][2], al[mt][3],
                         bh[nt][0], bh[nt][1]);
            }
    }
}

__device__ __forceinline__ void store_stage(SmemGemm* sm, int lrow, int kq, int bn, int kq4,
                                            const StageRegs& r) {
    *(uint4*)&sm->Ah[lrow * APS + kq]     = r.ah0;
    *(uint4*)&sm->Ah[lrow * APS + kq + 4] = r.ah1;
    *(uint4*)&sm->Al[lrow * APS + kq]     = r.al0;
    *(uint4*)&sm->Al[lrow * APS + kq + 4] = r.al1;
    *(uint4*)&sm->Bh[bn * BPS + kq4] = r.bh;
    *(uint4*)&sm->Bl[bn * BPS + kq4] = r.bl;
}

// GEMM1: h = relu([agg_mean | x] @ [W1_l; W1_r] + b1) -> split bf16 g_hh/g_hl.
__global__ __launch_bounds__(256) void gemm1_kernel(const float* __restrict__ b1) {
    __shared__ SmemGemm sm;
    int tid = threadIdx.x;
    int row0 = blockIdx.x * 128;
    int col0 = blockIdx.y * 64;
    int wid = tid >> 5, lane = tid & 31;
    int g = lane >> 2, tig = lane & 3;
    int wm = (wid & 3) * 32;
    int wn = (wid >> 2) * 32;

    int lrow = tid >> 1;
    int kq = (tid & 1) * 8;
    int arow = row0 + lrow;
    bool rowok = (arow < N_NODES);

    int bn = tid >> 2;               // 0..63
    int kq4 = (tid & 3) * 4;         // 0,4,8,12

    float acc[2][4][4];
#pragma unroll
    for (int mt = 0; mt < 2; mt++)
#pragma unroll
        for (int nt = 0; nt < 4; nt++)
#pragma unroll
            for (int i = 0; i < 4; i++) acc[mt][nt][i] = 0.f;

    auto load_stage = [&](int k0, StageRegs& r) {
        int kb = k0 >> 1;
        const uint32_t *srch, *srcl;
        if (kb < 64) {
            srch = &g_aggh[(size_t)arow * 64 + kb];
            srcl = &g_aggl[(size_t)arow * 64 + kb];
        } else {
            srch = &g_xbh[(size_t)arow * 64 + (kb - 64)];
            srcl = &g_xbl[(size_t)arow * 64 + (kb - 64)];
        }
        if (rowok) {
            r.ah0 = *(const uint4*)(srch + kq);
            r.ah1 = *(const uint4*)(srch + kq + 4);
            r.al0 = *(const uint4*)(srcl + kq);
            r.al1 = *(const uint4*)(srcl + kq + 4);
        } else {
            r.ah0 = r.ah1 = r.al0 = r.al1 = make_uint4(0, 0, 0, 0);
        }
        r.bh = *(const uint4*)&g_W1h[(size_t)(col0 + bn) * 128 + kb + kq4];
        r.bl = *(const uint4*)&g_W1l[(size_t)(col0 + bn) * 128 + kb + kq4];
    };

    StageRegs r;
    load_stage(0, r);
#pragma unroll
    for (int s = 0; s < 8; s++) {
        store_stage(&sm, lrow, kq, bn, kq4, r);
        __syncthreads();
        if (s < 7) load_stage((s + 1) * 32, r);   // latency overlaps compute below
        compute_chunk(&sm, wm, wn, g, tig, acc);
        __syncthreads();
    }

    // epilogue: relu(C + b1) -> split bf16 h
#pragma unroll
    for (int nt = 0; nt < 4; nt++) {
        int col = col0 + wn + nt * 8 + tig * 2;
        float2 bb = *(const float2*)&b1[col];
        int kpo = col >> 1;
#pragma unroll
        for (int mt = 0; mt < 2; mt++) {
            int r_lo = row0 + wm + mt * 16 + g;
            int r_hi = r_lo + 8;
            if (r_lo < N_NODES) {
                float v0 = fmaxf(acc[mt][nt][0] + bb.x, 0.f);
                float v1 = fmaxf(acc[mt][nt][1] + bb.y, 0.f);
                uint32_t ph, pl;
                split_pack2(v0, v1, ph, pl);
                g_hh[(size_t)r_lo * 128 + kpo] = ph;
                g_hl[(size_t)r_lo * 128 + kpo] = pl;
            }
            if (r_hi < N_NODES) {
                float v0 = fmaxf(acc[mt][nt][2] + bb.x, 0.f);
                float v1 = fmaxf(acc[mt][nt][3] + bb.y, 0.f);
                uint32_t ph, pl;
                split_pack2(v0, v1, ph, pl);
                g_hh[(size_t)r_hi * 128 + kpo] = ph;
                g_hl[(size_t)r_hi * 128 + kpo] = pl;
            }
        }
    }
}

// GEMM2: [p(bf16) | out=q+b2] = h @ [W2_l | W2_r].  K=256, virtual N=256.
__global__ __launch_bounds__(256) void gemm2_kernel(const float* __restrict__ b2,
                                                    float* __restrict__ out) {
    __shared__ SmemGemm sm;
    int tid = threadIdx.x;
    int row0 = blockIdx.x * 128;
    int col0 = blockIdx.y * 64;   // virtual col in [0,256)
    int wid = tid >> 5, lane = tid & 31;
    int g = lane >> 2, tig = lane & 3;
    int wm = (wid & 3) * 32;
    int wn = (wid >> 2) * 32;

    int lrow = tid >> 1;
    int kq = (tid & 1) * 8;
    int arow = row0 + lrow;
    bool rowok = (arow < N_NODES);

    int bn = tid >> 2;
    int kq4 = (tid & 3) * 4;

    float acc[2][4][4];
#pragma unroll
    for (int mt = 0; mt < 2; mt++)
#pragma unroll
        for (int nt = 0; nt < 4; nt++)
#pragma unroll
            for (int i = 0; i < 4; i++) acc[mt][nt][i] = 0.f;

    auto load_stage = [&](int k0, StageRegs& r) {
        int kb = k0 >> 1;
        if (rowok) {
            const uint32_t* srch = &g_hh[(size_t)arow * 128 + kb];
            const uint32_t* srcl = &g_hl[(size_t)arow * 128 + kb];
            r.ah0 = *(const uint4*)(srch + kq);
            r.ah1 = *(const uint4*)(srch + kq + 4);
            r.al0 = *(const uint4*)(srcl + kq);
            r.al1 = *(const uint4*)(srcl + kq + 4);
        } else {
            r.ah0 = r.ah1 = r.al0 = r.al1 = make_uint4(0, 0, 0, 0);
        }
        r.bh = *(const uint4*)&g_W2h[(size_t)(col0 + bn) * 128 + kb + kq4];
        r.bl = *(const uint4*)&g_W2l[(size_t)(col0 + bn) * 128 + kb + kq4];
    };

    StageRegs r;
    load_stage(0, r);
#pragma unroll
    for (int s = 0; s < 8; s++) {
        store_stage(&sm, lrow, kq, bn, kq4, r);
        __syncthreads();
        if (s < 7) load_stage((s + 1) * 32, r);
        compute_chunk(&sm, wm, wn, g, tig, acc);
        __syncthreads();
    }

    // epilogue: col<128 -> bf16 p;  col>=128 -> out = C + b2
#pragma unroll
    for (int nt = 0; nt < 4; nt++) {
        int col = col0 + wn + nt * 8 + tig * 2;   // virtual col
#pragma unroll
        for (int mt = 0; mt < 2; mt++) {
            int r_lo = row0 + wm + mt * 16 + g;
            int r_hi = r_lo + 8;
            if (col < 128) {
                int kpo = col >> 1;
                if (r_lo < N_NODES) {
                    __nv_bfloat162 v = __floats2bfloat162_rn(acc[mt][nt][0], acc[mt][nt][1]);
                    g_pb[(size_t)r_lo * 64 + kpo] = *(uint32_t*)&v;
                }
                if (r_hi < N_NODES) {
                    __nv_bfloat162 v = __floats2bfloat162_rn(acc[mt][nt][2], acc[mt][nt][3]);
                    g_pb[(size_t)r_hi * 64 + kpo] = *(uint32_t*)&v;
                }
            } else {
                int c = col - 128;
                float2 bb = *(const float2*)&b2[c];
                if (r_lo < N_NODES) {
                    float2 v;
                    v.x = acc[mt][nt][0] + bb.x;
                    v.y = acc[mt][nt][1] + bb.y;
                    *(float2*)&out[(size_t)r_lo * 128 + c] = v;
                }
                if (r_hi < N_NODES) {
                    float2 v;
                    v.x = acc[mt][nt][2] + bb.x;
                    v.y = acc[mt][nt][3] + bb.y;
                    *(float2*)&out[(size_t)r_hi * 128 + c] = v;
                }
            }
        }
    }
}

// ---------------- launch ----------------
extern "C" void kernel_launch(void* const* d_in, const int* in_sizes, int n_in,
                              void* d_out, int out_size) {
    const float* x   = (const float*)d_in[0];
    const int*   ei  = (const int*)d_in[1];   // int64 in reference -> int32 in harness
    const float* W1l = (const float*)d_in[2];
    const float* b1  = (const float*)d_in[3];
    const float* W1r = (const float*)d_in[4];
    const float* W2l = (const float*)d_in[5];
    const float* b2  = (const float*)d_in[6];
    const float* W2r = (const float*)d_in[7];
    float* out = (float*)d_out;

    // fused init (zero deg + split x + split/transposed weights)
    init_kernel<<<(N_NODES * 128 / 4 + 255) / 256, 256>>>(x, W1l, W1r, W2l, W2r);

    // CSR build
    hist_kernel<<<(N_E / 4 + 255) / 256, 256>>>(ei);
    scan_kernel<<<1, 1024>>>();
    scatter_kernel<<<(N_E / 4 + 255) / 256, 256>>>(ei);

    // Layer 1
    aggregate_x_kernel<<<(N_NODES + 7) / 8, 256>>>();
    {
        dim3 grid((N_NODES + 127) / 128, 4);
        gemm1_kernel<<<grid, 256>>>(b1);
    }

    // Layer 2
    {
        dim3 grid((N_NODES + 127) / 128, 4);
        gemm2_kernel<<<grid, 256>>>(b2, out);
    }
    aggregate_p_kernel<<<(N_NODES + 7) / 8, 256>>>(out);
}

// round 16
// speedup vs baseline: 1.4358x; 1.0341x over previous
#include <cuda_runtime.h>
#include <cuda_bf16.h>
#include <cstdint>

#define N_NODES 10000
#define N_E     640000
#define IN_DIM  128
#define HID_DIM 256
#define OUT_DIM 128

// ---------------- scratch (device globals; no allocation allowed) ----------------
__device__ int   g_deg[N_NODES];          // zero at load; re-zeroed by scan each launch
__device__ float g_invdeg[N_NODES];
__device__ int   g_off[N_NODES + 1];
__device__ int   g_rank[N_E];             // per-edge rank within destination (from hist)
__device__ int   g_csr[N_E];

// split-bf16 operand arrays (packed bf16x2 k-pairs, uint32 words)
__device__ __align__(16) uint32_t g_xbh[N_NODES * 64];   // x hi   [row][64 kpairs]
__device__ __align__(16) uint32_t g_xbl[N_NODES * 64];   // x lo
__device__ __align__(16) uint32_t g_aggh[N_NODES * 64];  // mean-agg hi
__device__ __align__(16) uint32_t g_aggl[N_NODES * 64];  // mean-agg lo
__device__ __align__(16) uint32_t g_hh[N_NODES * 128];   // h hi   [row][128 kpairs]
__device__ __align__(16) uint32_t g_hl[N_NODES * 128];   // h lo
__device__ __align__(16) uint32_t g_pb[N_NODES * 64];    // p bf16 (hi only, gather source)
// transposed split weights [n][kpair], 256 n x 128 kpairs each
__device__ __align__(16) uint32_t g_W1h[256 * 128];
__device__ __align__(16) uint32_t g_W1l[256 * 128];
__device__ __align__(16) uint32_t g_W2h[256 * 128];
__device__ __align__(16) uint32_t g_W2l[256 * 128];

// ---------------- split helpers ----------------
__device__ __forceinline__ void split_bf16(float v, __nv_bfloat16& hi, __nv_bfloat16& lo) {
    hi = __float2bfloat16_rn(v);
    lo = __float2bfloat16_rn(v - __bfloat162float(hi));
}

__device__ __forceinline__ void split_pack2(float v0, float v1, uint32_t& ph, uint32_t& pl) {
    __nv_bfloat16 h0, l0, h1, l1;
    split_bf16(v0, h0, l0);
    split_bf16(v1, h1, l1);
    __nv_bfloat162 hh; hh.x = h0; hh.y = h1;
    __nv_bfloat162 ll; ll.x = l0; ll.y = l1;
    ph = *(uint32_t*)&hh;
    pl = *(uint32_t*)&ll;
}

// ---------------- CSR build ----------------
// hist: degree count; atomic return value IS the edge's rank within its dst.
__global__ void hist_kernel(const int* __restrict__ ei) {
    int e4 = blockIdx.x * 256 + threadIdx.x;
    if (e4 < N_E / 4) {
        int4 d = ((const int4*)(ei + N_E))[e4];
        int4 r;
        r.x = atomicAdd(&g_deg[d.x], 1);
        r.y = atomicAdd(&g_deg[d.y], 1);
        r.z = atomicAdd(&g_deg[d.z], 1);
        r.w = atomicAdd(&g_deg[d.w], 1);
        ((int4*)g_rank)[e4] = r;
    }
}

// Single-block exclusive scan over 10000 degrees (1024 threads, 10 elems/thread).
// Also re-zeroes g_deg so the next graph replay starts clean (deterministic).
__global__ void scan_kernel() {
    __shared__ int sh[1024];
    const int CH = 10;
    int tid = threadIdx.x;
    int base = tid * CH;
    int loc[CH];
    int dval[CH];
    int s = 0;
#pragma unroll
    for (int i = 0; i < CH; i++) {
        int idx = base + i;
        int d = (idx < N_NODES) ? g_deg[idx] : 0;
        dval[i] = d;
        loc[i] = s;
        s += d;
    }
    sh[tid] = s;
    __syncthreads();
    for (int off = 1; off < 1024; off <<= 1) {
        int v = (tid >= off) ? sh[tid - off] : 0;
        __syncthreads();
        sh[tid] += v;
        __syncthreads();
    }
    int ex = (tid == 0) ? 0 : sh[tid - 1];
#pragma unroll
    for (int i = 0; i < CH; i++) {
        int idx = base + i;
        if (idx < N_NODES) {
            g_off[idx] = ex + loc[i];
            g_invdeg[idx] = 1.0f / fmaxf((float)dval[i], 1.0f);
            g_deg[idx] = 0;   // reset for next replay
        }
    }
    if (tid == 0) g_off[N_NODES] = sh[1023];
}

// ---------------- fused scatter (atomic-free) + operand prep ----------------
__global__ void scatter_init_kernel(const int* __restrict__ ei,
                                    const float* __restrict__ x,
                                    const float* __restrict__ W1lx, const float* __restrict__ W1rx,
                                    const float* __restrict__ W2lx, const float* __restrict__ W2rx) {
    int i = blockIdx.x * 256 + threadIdx.x;
    // scatter: csr[off[dst] + rank] = src  (pure streaming, no atomics)
    if (i < N_E / 4) {
        int4 s = ((const int4*)ei)[i];
        int4 d = ((const int4*)(ei + N_E))[i];
        int4 r = ((const int4*)g_rank)[i];
        g_csr[g_off[d.x] + r.x] = s.x;
        g_csr[g_off[d.y] + r.y] = s.y;
        g_csr[g_off[d.z] + r.z] = s.z;
        g_csr[g_off[d.w] + r.w] = s.w;
    }
    // prep x: one float4 -> 2 kpairs
    if (i < N_NODES * 128 / 4) {
        float4 v = *(const float4*)&x[(size_t)i * 4];
        uint32_t h0, l0, h1, l1;
        split_pack2(v.x, v.y, h0, l0);
        split_pack2(v.z, v.w, h1, l1);
        uint2 hv; hv.x = h0; hv.y = h1;
        uint2 lv; lv.x = l0; lv.y = l1;
        *(uint2*)&g_xbh[(size_t)i * 2] = hv;
        *(uint2*)&g_xbl[(size_t)i * 2] = lv;
    }
    // prep weights (transposed split)
    if (i < 2 * 256 * 128) {
        int mat = i >> 15;          // 0: W1, 1: W2
        int n = (i >> 7) & 255;
        int kp = i & 127;
        int k = kp * 2;
        float v0, v1;
        if (mat == 0) {
            if (k < 128) { v0 = W1lx[(size_t)k * 256 + n]; v1 = W1lx[(size_t)(k + 1) * 256 + n]; }
            else         { v0 = W1rx[(size_t)(k - 128) * 256 + n]; v1 = W1rx[(size_t)(k - 127) * 256 + n]; }
            uint32_t ph, pl;
            split_pack2(v0, v1, ph, pl);
            g_W1h[n * 128 + kp] = ph;
            g_W1l[n * 128 + kp] = pl;
        } else {
            if (n < 128) { v0 = W2lx[(size_t)k * 128 + n]; v1 = W2lx[(size_t)(k + 1) * 128 + n]; }
            else         { v0 = W2rx[(size_t)k * 128 + (n - 128)]; v1 = W2rx[(size_t)(k + 1) * 128 + (n - 128)]; }
            uint32_t ph, pl;
            split_pack2(v0, v1, ph, pl);
            g_W2h[n * 128 + kp] = ph;
            g_W2l[n * 128 + kp] = pl;
        }
    }
}

// ---------------- aggregation: one warp per node, half-warp edge substreams ----------------
__device__ __forceinline__ void acc8(float* a, uint4 v) {
    float2 p0 = __bfloat1622float2(*(__nv_bfloat162*)&v.x);
    float2 p1 = __bfloat1622float2(*(__nv_bfloat162*)&v.y);
    float2 p2 = __bfloat1622float2(*(__nv_bfloat162*)&v.z);
    float2 p3 = __bfloat1622float2(*(__nv_bfloat162*)&v.w);
    a[0] += p0.x; a[1] += p0.y; a[2] += p1.x; a[3] += p1.y;
    a[4] += p2.x; a[5] += p2.y; a[6] += p3.x; a[7] += p3.y;
}

// Layer 1: mean of bf16 x rows -> split bf16 (g_aggh/g_aggl)
__global__ void aggregate_x_kernel() {
    int warp = threadIdx.x >> 5;
    int lane = threadIdx.x & 31;
    int n = blockIdx.x * 8 + warp;
    if (n >= N_NODES) return;
    int h = lane >> 4;          // substream 0/1
    int lh = lane & 15;
    int kp = lh * 4;            // 4 kpairs = 8 bf16 dims per lane
    int beg = g_off[n];
    int end = g_off[n + 1];
    float a[8] = {0.f, 0.f, 0.f, 0.f, 0.f, 0.f, 0.f, 0.f};
    int e = beg + h;
    for (; e + 2 < end; e += 4) {
        int s0 = g_csr[e];
        int s1 = g_csr[e + 2];
        uint4 v0 = *(const uint4*)&g_xbh[(size_t)s0 * 64 + kp];
        uint4 v1 = *(const uint4*)&g_xbh[(size_t)s1 * 64 + kp];
        acc8(a, v0);
        acc8(a, v1);
    }
    if (e < end) {
        int s0 = g_csr[e];
        uint4 v0 = *(const uint4*)&g_xbh[(size_t)s0 * 64 + kp];
        acc8(a, v0);
    }
#pragma unroll
    for (int i = 0; i < 8; i++) a[i] += __shfl_down_sync(0xffffffffu, a[i], 16);
    if (h == 0) {
        float inv = g_invdeg[n];
        uint4 hv, lv;
        split_pack2(a[0] * inv, a[1] * inv, hv.x, lv.x);
        split_pack2(a[2] * inv, a[3] * inv, hv.y, lv.y);
        split_pack2(a[4] * inv, a[5] * inv, hv.z, lv.z);
        split_pack2(a[6] * inv, a[7] * inv, hv.w, lv.w);
        *(uint4*)&g_aggh[(size_t)n * 64 + kp] = hv;
        *(uint4*)&g_aggl[(size_t)n * 64 + kp] = lv;
    }
}

// Layer 2: out[n] += mean of bf16 p rows (finalize fused)
__global__ void aggregate_p_kernel(float* __restrict__ out) {
    int warp = threadIdx.x >> 5;
    int lane = threadIdx.x & 31;
    int n = blockIdx.x * 8 + warp;
    if (n >= N_NODES) return;
    int h = lane >> 4;
    int lh = lane & 15;
    int kp = lh * 4;
    int beg = g_off[n];
    int end = g_off[n + 1];
    float a[8] = {0.f, 0.f, 0.f, 0.f, 0.f, 0.f, 0.f, 0.f};
    int e = beg + h;
    for (; e + 2 < end; e += 4) {
        int s0 = g_csr[e];
        int s1 = g_csr[e + 2];
        uint4 v0 = *(const uint4*)&g_pb[(size_t)s0 * 64 + kp];
        uint4 v1 = *(const uint4*)&g_pb[(size_t)s1 * 64 + kp];
        acc8(a, v0);
        acc8(a, v1);
    }
    if (e < end) {
        int s0 = g_csr[e];
        uint4 v0 = *(const uint4*)&g_pb[(size_t)s0 * 64 + kp];
        acc8(a, v0);
    }
#pragma unroll
    for (int i = 0; i < 8; i++) a[i] += __shfl_down_sync(0xffffffffu, a[i], 16);
    if (h == 0) {
        float inv = g_invdeg[n];
        int c = lh * 8;
        float4 o0 = *(float4*)&out[(size_t)n * 128 + c];
        float4 o1 = *(float4*)&out[(size_t)n * 128 + c + 4];
        o0.x += a[0] * inv; o0.y += a[1] * inv; o0.z += a[2] * inv; o0.w += a[3] * inv;
        o1.x += a[4] * inv; o1.y += a[5] * inv; o1.z += a[6] * inv; o1.w += a[7] * inv;
        *(float4*)&out[(size_t)n * 128 + c] = o0;
        *(float4*)&out[(size_t)n * 128 + c + 4] = o1;
    }
}

// ================= split-bf16 mma GEMMs (register-prefetch pipelined) =================
__device__ __forceinline__ void mma_bf16(float* c, uint32_t a0, uint32_t a1, uint32_t a2, uint32_t a3,
                                         uint32_t b0, uint32_t b1) {
    asm volatile(
        "mma.sync.aligned.m16n8k16.row.col.f32.bf16.bf16.f32 "
        "{%0,%1,%2,%3}, {%4,%5,%6,%7}, {%8,%9}, {%0,%1,%2,%3};"
        : "+f"(c[0]), "+f"(c[1]), "+f"(c[2]), "+f"(c[3])
        : "r"(a0), "r"(a1), "r"(a2), "r"(a3), "r"(b0), "r"(b1));
}

#define APS 20   // A kpair stride (uint32 words)
#define BPS 20   // B kpair stride (uint32 words)

struct SmemGemm {
    uint32_t Ah[128 * APS];
    uint32_t Al[128 * APS];
    uint32_t Bh[64 * BPS];
    uint32_t Bl[64 * BPS];
};

struct StageRegs {
    uint4 ah0, ah1, al0, al1;   // A: 8 kpairs hi + lo
    uint4 bh, bl;               // B: 4 kpairs hi + lo
};

__device__ __forceinline__ void compute_chunk(SmemGemm* sm, int wm, int wn, int g, int tig,
                                              float acc[2][4][4]) {
#pragma unroll
    for (int ks = 0; ks < 2; ks++) {
        int kp = ks * 8;
        uint32_t ah[2][4], al[2][4];
#pragma unroll
        for (int mt = 0; mt < 2; mt++) {
            const uint32_t* ph = &sm->Ah[(wm + mt * 16 + g) * APS + kp + tig];
            const uint32_t* pl = &sm->Al[(wm + mt * 16 + g) * APS + kp + tig];
            ah[mt][0] = ph[0];       al[mt][0] = pl[0];
            ah[mt][1] = ph[8 * APS]; al[mt][1] = pl[8 * APS];
            ah[mt][2] = ph[4];       al[mt][2] = pl[4];
            ah[mt][3] = ph[8 * APS + 4]; al[mt][3] = pl[8 * APS + 4];
        }
        uint32_t bh[4][2], bl[4][2];
#pragma unroll
        for (int nt = 0; nt < 4; nt++) {
            const uint32_t* ph = &sm->Bh[(wn + nt * 8 + g) * BPS + kp + tig];
            const uint32_t* pl = &sm->Bl[(wn + nt * 8 + g) * BPS + kp + tig];
            bh[nt][0] = ph[0]; bh[nt][1] = ph[4];
            bl[nt][0] = pl[0]; bl[nt][1] = pl[4];
        }
#pragma unroll
        for (int mt = 0; mt < 2; mt++)
#pragma unroll
            for (int nt = 0; nt < 4; nt++) {
                mma_bf16(acc[mt][nt], ah[mt][0], ah[mt][1], ah[mt][2], ah[mt][3],
                         bh[nt][0], bh[nt][1]);
                mma_bf16(acc[mt][nt], ah[mt][0], ah[mt][1], ah[mt][2], ah[mt][3],
                         bl[nt][0], bl[nt][1]);
                mma_bf16(acc[mt][nt], al[mt][0], al[mt][1], al[mt][2], al[mt][3],
                         bh[nt][0], bh[nt][1]);
            }
    }
}

__device__ __forceinline__ void store_stage(SmemGemm* sm, int lrow, int kq, int bn, int kq4,
                                            const StageRegs& r) {
    *(uint4*)&sm->Ah[lrow * APS + kq]     = r.ah0;
    *(uint4*)&sm->Ah[lrow * APS + kq + 4] = r.ah1;
    *(uint4*)&sm->Al[lrow * APS + kq]     = r.al0;
    *(uint4*)&sm->Al[lrow * APS + kq + 4] = r.al1;
    *(uint4*)&sm->Bh[bn * BPS + kq4] = r.bh;
    *(uint4*)&sm->Bl[bn * BPS + kq4] = r.bl;
}

// GEMM1: h = relu([agg_mean | x] @ [W1_l; W1_r] + b1) -> split bf16 g_hh/g_hl.
__global__ __launch_bounds__(256) void gemm1_kernel(const float* __restrict__ b1) {
    __shared__ SmemGemm sm;
    int tid = threadIdx.x;
    int row0 = blockIdx.x * 128;
    int col0 = blockIdx.y * 64;
    int wid = tid >> 5, lane = tid & 31;
    int g = lane >> 2, tig = lane & 3;
    int wm = (wid & 3) * 32;
    int wn = (wid >> 2) * 32;

    int lrow = tid >> 1;
    int kq = (tid & 1) * 8;
    int arow = row0 + lrow;
    bool rowok = (arow < N_NODES);

    int bn = tid >> 2;               // 0..63
    int kq4 = (tid & 3) * 4;         // 0,4,8,12

    float acc[2][4][4];
#pragma unroll
    for (int mt = 0; mt < 2; mt++)
#pragma unroll
        for (int nt = 0; nt < 4; nt++)
#pragma unroll
            for (int i = 0; i < 4; i++) acc[mt][nt][i] = 0.f;

    auto load_stage = [&](int k0, StageRegs& r) {
        int kb = k0 >> 1;
        const uint32_t *srch, *srcl;
        if (kb < 64) {
            srch = &g_aggh[(size_t)arow * 64 + kb];
            srcl = &g_aggl[(size_t)arow * 64 + kb];
        } else {
            srch = &g_xbh[(size_t)arow * 64 + (kb - 64)];
            srcl = &g_xbl[(size_t)arow * 64 + (kb - 64)];
        }
        if (rowok) {
            r.ah0 = *(const uint4*)(srch + kq);
            r.ah1 = *(const uint4*)(srch + kq + 4);
            r.al0 = *(const uint4*)(srcl + kq);
            r.al1 = *(const uint4*)(srcl + kq + 4);
        } else {
            r.ah0 = r.ah1 = r.al0 = r.al1 = make_uint4(0, 0, 0, 0);
        }
        r.bh = *(const uint4*)&g_W1h[(size_t)(col0 + bn) * 128 + kb + kq4];
        r.bl = *(const uint4*)&g_W1l[(size_t)(col0 + bn) * 128 + kb + kq4];
    };

    StageRegs r;
    load_stage(0, r);
#pragma unroll
    for (int s = 0; s < 8; s++) {
        store_stage(&sm, lrow, kq, bn, kq4, r);
        __syncthreads();
        if (s < 7) load_stage((s + 1) * 32, r);   // latency overlaps compute below
        compute_chunk(&sm, wm, wn, g, tig, acc);
        __syncthreads();
    }

    // epilogue: relu(C + b1) -> split bf16 h
#pragma unroll
    for (int nt = 0; nt < 4; nt++) {
        int col = col0 + wn + nt * 8 + tig * 2;
        float2 bb = *(const float2*)&b1[col];
        int kpo = col >> 1;
#pragma unroll
        for (int mt = 0; mt < 2; mt++) {
            int r_lo = row0 + wm + mt * 16 + g;
            int r_hi = r_lo + 8;
            if (r_lo < N_NODES) {
                float v0 = fmaxf(acc[mt][nt][0] + bb.x, 0.f);
                float v1 = fmaxf(acc[mt][nt][1] + bb.y, 0.f);
                uint32_t ph, pl;
                split_pack2(v0, v1, ph, pl);
                g_hh[(size_t)r_lo * 128 + kpo] = ph;
                g_hl[(size_t)r_lo * 128 + kpo] = pl;
            }
            if (r_hi < N_NODES) {
                float v0 = fmaxf(acc[mt][nt][2] + bb.x, 0.f);
                float v1 = fmaxf(acc[mt][nt][3] + bb.y, 0.f);
                uint32_t ph, pl;
                split_pack2(v0, v1, ph, pl);
                g_hh[(size_t)r_hi * 128 + kpo] = ph;
                g_hl[(size_t)r_hi * 128 + kpo] = pl;
            }
        }
    }
}

// GEMM2: [p(bf16) | out=q+b2] = h @ [W2_l | W2_r].  K=256, virtual N=256.
__global__ __launch_bounds__(256) void gemm2_kernel(const float* __restrict__ b2,
                                                    float* __restrict__ out) {
    __shared__ SmemGemm sm;
    int tid = threadIdx.x;
    int row0 = blockIdx.x * 128;
    int col0 = blockIdx.y * 64;   // virtual col in [0,256)
    int wid = tid >> 5, lane = tid & 31;
    int g = lane >> 2, tig = lane & 3;
    int wm = (wid & 3) * 32;
    int wn = (wid >> 2) * 32;

    int lrow = tid >> 1;
    int kq = (tid & 1) * 8;
    int arow = row0 + lrow;
    bool rowok = (arow < N_NODES);

    int bn = tid >> 2;
    int kq4 = (tid & 3) * 4;

    float acc[2][4][4];
#pragma unroll
    for (int mt = 0; mt < 2; mt++)
#pragma unroll
        for (int nt = 0; nt < 4; nt++)
#pragma unroll
            for (int i = 0; i < 4; i++) acc[mt][nt][i] = 0.f;

    auto load_stage = [&](int k0, StageRegs& r) {
        int kb = k0 >> 1;
        if (rowok) {
            const uint32_t* srch = &g_hh[(size_t)arow * 128 + kb];
            const uint32_t* srcl = &g_hl[(size_t)arow * 128 + kb];
            r.ah0 = *(const uint4*)(srch + kq);
            r.ah1 = *(const uint4*)(srch + kq + 4);
            r.al0 = *(const uint4*)(srcl + kq);
            r.al1 = *(const uint4*)(srcl + kq + 4);
        } else {
            r.ah0 = r.ah1 = r.al0 = r.al1 = make_uint4(0, 0, 0, 0);
        }
        r.bh = *(const uint4*)&g_W2h[(size_t)(col0 + bn) * 128 + kb + kq4];
        r.bl = *(const uint4*)&g_W2l[(size_t)(col0 + bn) * 128 + kb + kq4];
    };

    StageRegs r;
    load_stage(0, r);
#pragma unroll
    for (int s = 0; s < 8; s++) {
        store_stage(&sm, lrow, kq, bn, kq4, r);
        __syncthreads();
        if (s < 7) load_stage((s + 1) * 32, r);
        compute_chunk(&sm, wm, wn, g, tig, acc);
        __syncthreads();
    }

    // epilogue: col<128 -> bf16 p;  col>=128 -> out = C + b2
#pragma unroll
    for (int nt = 0; nt < 4; nt++) {
        int col = col0 + wn + nt * 8 + tig * 2;   // virtual col
#pragma unroll
        for (int mt = 0; mt < 2; mt++) {
            int r_lo = row0 + wm + mt * 16 + g;
            int r_hi = r_lo + 8;
            if (col < 128) {
                int kpo = col >> 1;
                if (r_lo < N_NODES) {
                    __nv_bfloat162 v = __floats2bfloat162_rn(acc[mt][nt][0], acc[mt][nt][1]);
                    g_pb[(size_t)r_lo * 64 + kpo] = *(uint32_t*)&v;
                }
                if (r_hi < N_NODES) {
                    __nv_bfloat162 v = __floats2bfloat162_rn(acc[mt][nt][2], acc[mt][nt][3]);
                    g_pb[(size_t)r_hi * 64 + kpo] = *(uint32_t*)&v;
                }
            } else {
                int c = col - 128;
                float2 bb = *(const float2*)&b2[c];
                if (r_lo < N_NODES) {
                    float2 v;
                    v.x = acc[mt][nt][0] + bb.x;
                    v.y = acc[mt][nt][1] + bb.y;
                    *(float2*)&out[(size_t)r_lo * 128 + c] = v;
                }
                if (r_hi < N_NODES) {
                    float2 v;
                    v.x = acc[mt][nt][2] + bb.x;
                    v.y = acc[mt][nt][3] + bb.y;
                    *(float2*)&out[(size_t)r_hi * 128 + c] = v;
                }
            }
        }
    }
}

// ---------------- launch ----------------
extern "C" void kernel_launch(void* const* d_in, const int* in_sizes, int n_in,
                              void* d_out, int out_size) {
    const float* x   = (const float*)d_in[0];
    const int*   ei  = (const int*)d_in[1];   // int64 in reference -> int32 in harness
    const float* W1l = (const float*)d_in[2];
    const float* b1  = (const float*)d_in[3];
    const float* W1r = (const float*)d_in[4];
    const float* W2l = (const float*)d_in[5];
    const float* b2  = (const float*)d_in[6];
    const float* W2r = (const float*)d_in[7];
    float* out = (float*)d_out;

    // CSR build: hist (atomics + rank), scan (offsets + deg reset), atomic-free scatter
    hist_kernel<<<(N_E / 4 + 255) / 256, 256>>>(ei);
    scan_kernel<<<1, 1024>>>();
    // fused: atomic-free scatter + split x + split/transposed weights
    scatter_init_kernel<<<(N_NODES * 128 / 4 + 255) / 256, 256>>>(ei, x, W1l, W1r, W2l, W2r);

    // Layer 1
    aggregate_x_kernel<<<(N_NODES + 7) / 8, 256>>>();
    {
        dim3 grid((N_NODES + 127) / 128, 4);
        gemm1_kernel<<<grid, 256>>>(b1);
    }

    // Layer 2
    {
        dim3 grid((N_NODES + 127) / 128, 4);
        gemm2_kernel<<<grid, 256>>>(b2, out);
    }
    aggregate_p_kernel<<<(N_NODES + 7) / 8, 256>>>(out);
}

// round 17
// speedup vs baseline: 1.5008x; 1.0452x over previous
#include <cuda_runtime.h>
#include <cuda_bf16.h>
#include <cstdint>

#define N_NODES 10000
#define N_E     640000
#define IN_DIM  128
#define HID_DIM 256
#define OUT_DIM 128

// ---------------- scratch (device globals; no allocation allowed) ----------------
__device__ int   g_deg[N_NODES];          // zero at load; re-zeroed by scan each launch
__device__ float g_invdeg[N_NODES];
__device__ int   g_off[N_NODES + 1];
__device__ int   g_rank[N_E];             // per-edge rank within destination (from hist)
__device__ int   g_csr[N_E];

// split-bf16 operand arrays (packed bf16x2 k-pairs, uint32 words)
__device__ __align__(16) uint32_t g_xbh[N_NODES * 64];   // x hi   [row][64 kpairs]
__device__ __align__(16) uint32_t g_xbl[N_NODES * 64];   // x lo
__device__ __align__(16) uint32_t g_aggh[N_NODES * 64];  // mean-agg hi
__device__ __align__(16) uint32_t g_aggl[N_NODES * 64];  // mean-agg lo
__device__ __align__(16) uint32_t g_hh[N_NODES * 128];   // h hi   [row][128 kpairs]
__device__ __align__(16) uint32_t g_hl[N_NODES * 128];   // h lo
__device__ __align__(16) uint32_t g_pb[N_NODES * 64];    // p bf16 (hi only, gather source)
// transposed split weights [n][kpair], 256 n x 128 kpairs each
__device__ __align__(16) uint32_t g_W1h[256 * 128];
__device__ __align__(16) uint32_t g_W1l[256 * 128];
__device__ __align__(16) uint32_t g_W2h[256 * 128];
__device__ __align__(16) uint32_t g_W2l[256 * 128];

// ---------------- split helpers ----------------
__device__ __forceinline__ void split_bf16(float v, __nv_bfloat16& hi, __nv_bfloat16& lo) {
    hi = __float2bfloat16_rn(v);
    lo = __float2bfloat16_rn(v - __bfloat162float(hi));
}

__device__ __forceinline__ void split_pack2(float v0, float v1, uint32_t& ph, uint32_t& pl) {
    __nv_bfloat16 h0, l0, h1, l1;
    split_bf16(v0, h0, l0);
    split_bf16(v1, h1, l1);
    __nv_bfloat162 hh; hh.x = h0; hh.y = h1;
    __nv_bfloat162 ll; ll.x = l0; ll.y = l1;
    ph = *(uint32_t*)&hh;
    pl = *(uint32_t*)&ll;
}

// ---------------- CSR build ----------------
// hist: degree count; atomic return value IS the edge's rank within its dst.
__global__ void hist_kernel(const int* __restrict__ ei) {
    int e4 = blockIdx.x * 256 + threadIdx.x;
    if (e4 < N_E / 4) {
        int4 d = ((const int4*)(ei + N_E))[e4];
        int4 r;
        r.x = atomicAdd(&g_deg[d.x], 1);
        r.y = atomicAdd(&g_deg[d.y], 1);
        r.z = atomicAdd(&g_deg[d.z], 1);
        r.w = atomicAdd(&g_deg[d.w], 1);
        ((int4*)g_rank)[e4] = r;
    }
}

// Single-block exclusive scan over 10000 degrees (1024 threads, 10 elems/thread).
// Also re-zeroes g_deg so the next graph replay starts clean (deterministic).
__global__ void scan_kernel() {
    __shared__ int sh[1024];
    const int CH = 10;
    int tid = threadIdx.x;
    int base = tid * CH;
    int loc[CH];
    int dval[CH];
    int s = 0;
#pragma unroll
    for (int i = 0; i < CH; i++) {
        int idx = base + i;
        int d = (idx < N_NODES) ? g_deg[idx] : 0;
        dval[i] = d;
        loc[i] = s;
        s += d;
    }
    sh[tid] = s;
    __syncthreads();
    for (int off = 1; off < 1024; off <<= 1) {
        int v = (tid >= off) ? sh[tid - off] : 0;
        __syncthreads();
        sh[tid] += v;
        __syncthreads();
    }
    int ex = (tid == 0) ? 0 : sh[tid - 1];
#pragma unroll
    for (int i = 0; i < CH; i++) {
        int idx = base + i;
        if (idx < N_NODES) {
            g_off[idx] = ex + loc[i];
            g_invdeg[idx] = 1.0f / fmaxf((float)dval[i], 1.0f);
            g_deg[idx] = 0;   // reset for next replay
        }
    }
    if (tid == 0) g_off[N_NODES] = sh[1023];
}

// ---------------- fused scatter (atomic-free) + operand prep ----------------
__global__ void scatter_init_kernel(const int* __restrict__ ei,
                                    const float* __restrict__ x,
                                    const float* __restrict__ W1lx, const float* __restrict__ W1rx,
                                    const float* __restrict__ W2lx, const float* __restrict__ W2rx) {
    int i = blockIdx.x * 256 + threadIdx.x;
    // scatter: csr[off[dst] + rank] = src  (pure streaming, no atomics)
    if (i < N_E / 4) {
        int4 s = ((const int4*)ei)[i];
        int4 d = ((const int4*)(ei + N_E))[i];
        int4 r = ((const int4*)g_rank)[i];
        g_csr[g_off[d.x] + r.x] = s.x;
        g_csr[g_off[d.y] + r.y] = s.y;
        g_csr[g_off[d.z] + r.z] = s.z;
        g_csr[g_off[d.w] + r.w] = s.w;
    }
    // prep x: one float4 -> 2 kpairs
    if (i < N_NODES * 128 / 4) {
        float4 v = *(const float4*)&x[(size_t)i * 4];
        uint32_t h0, l0, h1, l1;
        split_pack2(v.x, v.y, h0, l0);
        split_pack2(v.z, v.w, h1, l1);
        uint2 hv; hv.x = h0; hv.y = h1;
        uint2 lv; lv.x = l0; lv.y = l1;
        *(uint2*)&g_xbh[(size_t)i * 2] = hv;
        *(uint2*)&g_xbl[(size_t)i * 2] = lv;
    }
    // prep weights (transposed split)
    if (i < 2 * 256 * 128) {
        int mat = i >> 15;          // 0: W1, 1: W2
        int n = (i >> 7) & 255;
        int kp = i & 127;
        int k = kp * 2;
        float v0, v1;
        if (mat == 0) {
            if (k < 128) { v0 = W1lx[(size_t)k * 256 + n]; v1 = W1lx[(size_t)(k + 1) * 256 + n]; }
            else         { v0 = W1rx[(size_t)(k - 128) * 256 + n]; v1 = W1rx[(size_t)(k - 127) * 256 + n]; }
            uint32_t ph, pl;
            split_pack2(v0, v1, ph, pl);
            g_W1h[n * 128 + kp] = ph;
            g_W1l[n * 128 + kp] = pl;
        } else {
            if (n < 128) { v0 = W2lx[(size_t)k * 128 + n]; v1 = W2lx[(size_t)(k + 1) * 128 + n]; }
            else         { v0 = W2rx[(size_t)k * 128 + (n - 128)]; v1 = W2rx[(size_t)(k + 1) * 128 + (n - 128)]; }
            uint32_t ph, pl;
            split_pack2(v0, v1, ph, pl);
            g_W2h[n * 128 + kp] = ph;
            g_W2l[n * 128 + kp] = pl;
        }
    }
}

// ---------------- aggregation: one warp per node, half-warp edge substreams ----------------
// Packed f32x2 accumulation: each bf16x2 word w contributes lo=w<<16, hi=w&0xffff0000,
// both added with one add.rn.f32x2. Bit-identical to scalar FADD per element.
__device__ __forceinline__ void accw_f32x2(uint64_t& acc, uint32_t w) {
    uint32_t lo = w << 16;
    uint32_t hi = w & 0xffff0000u;
    uint64_t v;
    asm("mov.b64 %0, {%1,%2};" : "=l"(v) : "r"(lo), "r"(hi));
    asm("add.rn.f32x2 %0, %0, %1;" : "+l"(acc) : "l"(v));
}

__device__ __forceinline__ void acc8p(uint64_t* a, uint4 v) {
    accw_f32x2(a[0], v.x);
    accw_f32x2(a[1], v.y);
    accw_f32x2(a[2], v.z);
    accw_f32x2(a[3], v.w);
}

// Layer 1: mean of bf16 x rows -> split bf16 (g_aggh/g_aggl)
__global__ void aggregate_x_kernel() {
    int warp = threadIdx.x >> 5;
    int lane = threadIdx.x & 31;
    int n = blockIdx.x * 8 + warp;
    if (n >= N_NODES) return;
    int h = lane >> 4;          // substream 0/1
    int lh = lane & 15;
    uint32_t kp = (uint32_t)lh * 4u;   // 4 kpairs = 8 bf16 dims per lane
    int beg = g_off[n];
    int end = g_off[n + 1];
    uint64_t a[4] = {0ull, 0ull, 0ull, 0ull};
    int e = beg + h;
    // 4 edges per substream iteration (8 per warp)
    for (; e + 6 < end; e += 8) {
        int s0 = g_csr[e];
        int s1 = g_csr[e + 2];
        int s2 = g_csr[e + 4];
        int s3 = g_csr[e + 6];
        uint4 v0 = *(const uint4*)(g_xbh + (uint32_t)s0 * 64u + kp);
        uint4 v1 = *(const uint4*)(g_xbh + (uint32_t)s1 * 64u + kp);
        uint4 v2 = *(const uint4*)(g_xbh + (uint32_t)s2 * 64u + kp);
        uint4 v3 = *(const uint4*)(g_xbh + (uint32_t)s3 * 64u + kp);
        acc8p(a, v0);
        acc8p(a, v1);
        acc8p(a, v2);
        acc8p(a, v3);
    }
    for (; e < end; e += 2) {
        int s0 = g_csr[e];
        uint4 v0 = *(const uint4*)(g_xbh + (uint32_t)s0 * 64u + kp);
        acc8p(a, v0);
    }
    // unpack packed pairs to 8 floats
    float f[8];
#pragma unroll
    for (int i = 0; i < 4; i++) {
        f[2 * i]     = __uint_as_float((uint32_t)a[i]);
        f[2 * i + 1] = __uint_as_float((uint32_t)(a[i] >> 32));
    }
#pragma unroll
    for (int i = 0; i < 8; i++) f[i] += __shfl_down_sync(0xffffffffu, f[i], 16);
    if (h == 0) {
        float inv = g_invdeg[n];
        uint4 hv, lv;
        split_pack2(f[0] * inv, f[1] * inv, hv.x, lv.x);
        split_pack2(f[2] * inv, f[3] * inv, hv.y, lv.y);
        split_pack2(f[4] * inv, f[5] * inv, hv.z, lv.z);
        split_pack2(f[6] * inv, f[7] * inv, hv.w, lv.w);
        *(uint4*)(g_aggh + (uint32_t)n * 64u + kp) = hv;
        *(uint4*)(g_aggl + (uint32_t)n * 64u + kp) = lv;
    }
}

// Layer 2: out[n] += mean of bf16 p rows (finalize fused)
__global__ void aggregate_p_kernel(float* __restrict__ out) {
    int warp = threadIdx.x >> 5;
    int lane = threadIdx.x & 31;
    int n = blockIdx.x * 8 + warp;
    if (n >= N_NODES) return;
    int h = lane >> 4;
    int lh = lane & 15;
    uint32_t kp = (uint32_t)lh * 4u;
    int beg = g_off[n];
    int end = g_off[n + 1];
    uint64_t a[4] = {0ull, 0ull, 0ull, 0ull};
    int e = beg + h;
    for (; e + 6 < end; e += 8) {
        int s0 = g_csr[e];
        int s1 = g_csr[e + 2];
        int s2 = g_csr[e + 4];
        int s3 = g_csr[e + 6];
        uint4 v0 = *(const uint4*)(g_pb + (uint32_t)s0 * 64u + kp);
        uint4 v1 = *(const uint4*)(g_pb + (uint32_t)s1 * 64u + kp);
        uint4 v2 = *(const uint4*)(g_pb + (uint32_t)s2 * 64u + kp);
        uint4 v3 = *(const uint4*)(g_pb + (uint32_t)s3 * 64u + kp);
        acc8p(a, v0);
        acc8p(a, v1);
        acc8p(a, v2);
        acc8p(a, v3);
    }
    for (; e < end; e += 2) {
        int s0 = g_csr[e];
        uint4 v0 = *(const uint4*)(g_pb + (uint32_t)s0 * 64u + kp);
        acc8p(a, v0);
    }
    float f[8];
#pragma unroll
    for (int i = 0; i < 4; i++) {
        f[2 * i]     = __uint_as_float((uint32_t)a[i]);
        f[2 * i + 1] = __uint_as_float((uint32_t)(a[i] >> 32));
    }
#pragma unroll
    for (int i = 0; i < 8; i++) f[i] += __shfl_down_sync(0xffffffffu, f[i], 16);
    if (h == 0) {
        float inv = g_invdeg[n];
        int c = lh * 8;
        float4 o0 = *(float4*)&out[(size_t)n * 128 + c];
        float4 o1 = *(float4*)&out[(size_t)n * 128 + c + 4];
        o0.x += f[0] * inv; o0.y += f[1] * inv; o0.z += f[2] * inv; o0.w += f[3] * inv;
        o1.x += f[4] * inv; o1.y += f[5] * inv; o1.z += f[6] * inv; o1.w += f[7] * inv;
        *(float4*)&out[(size_t)n * 128 + c] = o0;
        *(float4*)&out[(size_t)n * 128 + c + 4] = o1;
    }
}

// ================= split-bf16 mma GEMMs (register-prefetch pipelined) =================
__device__ __forceinline__ void mma_bf16(float* c, uint32_t a0, uint32_t a1, uint32_t a2, uint32_t a3,
                                         uint32_t b0, uint32_t b1) {
    asm volatile(
        "mma.sync.aligned.m16n8k16.row.col.f32.bf16.bf16.f32 "
        "{%0,%1,%2,%3}, {%4,%5,%6,%7}, {%8,%9}, {%0,%1,%2,%3};"
        : "+f"(c[0]), "+f"(c[1]), "+f"(c[2]), "+f"(c[3])
        : "r"(a0), "r"(a1), "r"(a2), "r"(a3), "r"(b0), "r"(b1));
}

#define APS 20   // A kpair stride (uint32 words)
#define BPS 20   // B kpair stride (uint32 words)

struct SmemGemm {
    uint32_t Ah[128 * APS];
    uint32_t Al[128 * APS];
    uint32_t Bh[64 * BPS];
    uint32_t Bl[64 * BPS];
};

struct StageRegs {
    uint4 ah0, ah1, al0, al1;   // A: 8 kpairs hi + lo
    uint4 bh, bl;               // B: 4 kpairs hi + lo
};

__device__ __forceinline__ void compute_chunk(SmemGemm* sm, int wm, int wn, int g, int tig,
                                              float acc[2][4][4]) {
#pragma unroll
    for (int ks = 0; ks < 2; ks++) {
        int kp = ks * 8;
        uint32_t ah[2][4], al[2][4];
#pragma unroll
        for (int mt = 0; mt < 2; mt++) {
            const uint32_t* ph = &sm->Ah[(wm + mt * 16 + g) * APS + kp + tig];
            const uint32_t* pl = &sm->Al[(wm + mt * 16 + g) * APS + kp + tig];
            ah[mt][0] = ph[0];       al[mt][0] = pl[0];
            ah[mt][1] = ph[8 * APS]; al[mt][1] = pl[8 * APS];
            ah[mt][2] = ph[4];       al[mt][2] = pl[4];
            ah[mt][3] = ph[8 * APS + 4]; al[mt][3] = pl[8 * APS + 4];
        }
        uint32_t bh[4][2], bl[4][2];
#pragma unroll
        for (int nt = 0; nt < 4; nt++) {
            const uint32_t* ph = &sm->Bh[(wn + nt * 8 + g) * BPS + kp + tig];
            const uint32_t* pl = &sm->Bl[(wn + nt * 8 + g) * BPS + kp + tig];
            bh[nt][0] = ph[0]; bh[nt][1] = ph[4];
            bl[nt][0] = pl[0]; bl[nt][1] = pl[4];
        }
#pragma unroll
        for (int mt = 0; mt < 2; mt++)
#pragma unroll
            for (int nt = 0; nt < 4; nt++) {
                mma_bf16(acc[mt][nt], ah[mt][0], ah[mt][1], ah[mt][2], ah[mt][3],
                         bh[nt][0], bh[nt][1]);
                mma_bf16(acc[mt][nt], ah[mt][0], ah[mt][1], ah[mt][2], ah[mt][3],
                         bl[nt][0], bl[nt][1]);
                mma_bf16(acc[mt][nt], al[mt][0], al[mt][1], al[mt][2], al[mt][3],
                         bh[nt][0], bh[nt][1]);
            }
    }
}

__device__ __forceinline__ void store_stage(SmemGemm* sm, int lrow, int kq, int bn, int kq4,
                                            const StageRegs& r) {
    *(uint4*)&sm->Ah[lrow * APS + kq]     = r.ah0;
    *(uint4*)&sm->Ah[lrow * APS + kq + 4] = r.ah1;
    *(uint4*)&sm->Al[lrow * APS + kq]     = r.al0;
    *(uint4*)&sm->Al[lrow * APS + kq + 4] = r.al1;
    *(uint4*)&sm->Bh[bn * BPS + kq4] = r.bh;
    *(uint4*)&sm->Bl[bn * BPS + kq4] = r.bl;
}

// GEMM1: h = relu([agg_mean | x] @ [W1_l; W1_r] + b1) -> split bf16 g_hh/g_hl.
__global__ __launch_bounds__(256) void gemm1_kernel(const float* __restrict__ b1) {
    __shared__ SmemGemm sm;
    int tid = threadIdx.x;
    int row0 = blockIdx.x * 128;
    int col0 = blockIdx.y * 64;
    int wid = tid >> 5, lane = tid & 31;
    int g = lane >> 2, tig = lane & 3;
    int wm = (wid & 3) * 32;
    int wn = (wid >> 2) * 32;

    int lrow = tid >> 1;
    int kq = (tid & 1) * 8;
    int arow = row0 + lrow;
    bool rowok = (arow < N_NODES);

    int bn = tid >> 2;               // 0..63
    int kq4 = (tid & 3) * 4;         // 0,4,8,12

    float acc[2][4][4];
#pragma unroll
    for (int mt = 0; mt < 2; mt++)
#pragma unroll
        for (int nt = 0; nt < 4; nt++)
#pragma unroll
            for (int i = 0; i < 4; i++) acc[mt][nt][i] = 0.f;

    auto load_stage = [&](int k0, StageRegs& r) {
        int kb = k0 >> 1;
        const uint32_t *srch, *srcl;
        if (kb < 64) {
            srch = &g_aggh[(size_t)arow * 64 + kb];
            srcl = &g_aggl[(size_t)arow * 64 + kb];
        } else {
            srch = &g_xbh[(size_t)arow * 64 + (kb - 64)];
            srcl = &g_xbl[(size_t)arow * 64 + (kb - 64)];
        }
        if (rowok) {
            r.ah0 = *(const uint4*)(srch + kq);
            r.ah1 = *(const uint4*)(srch + kq + 4);
            r.al0 = *(const uint4*)(srcl + kq);
            r.al1 = *(const uint4*)(srcl + kq + 4);
        } else {
            r.ah0 = r.ah1 = r.al0 = r.al1 = make_uint4(0, 0, 0, 0);
        }
        r.bh = *(const uint4*)&g_W1h[(size_t)(col0 + bn) * 128 + kb + kq4];
        r.bl = *(const uint4*)&g_W1l[(size_t)(col0 + bn) * 128 + kb + kq4];
    };

    StageRegs r;
    load_stage(0, r);
#pragma unroll
    for (int s = 0; s < 8; s++) {
        store_stage(&sm, lrow, kq, bn, kq4, r);
        __syncthreads();
        if (s < 7) load_stage((s + 1) * 32, r);   // latency overlaps compute below
        compute_chunk(&sm, wm, wn, g, tig, acc);
        __syncthreads();
    }

    // epilogue: relu(C + b1) -> split bf16 h
#pragma unroll
    for (int nt = 0; nt < 4; nt++) {
        int col = col0 + wn + nt * 8 + tig * 2;
        float2 bb = *(const float2*)&b1[col];
        int kpo = col >> 1;
#pragma unroll
        for (int mt = 0; mt < 2; mt++) {
            int r_lo = row0 + wm + mt * 16 + g;
            int r_hi = r_lo + 8;
            if (r_lo < N_NODES) {
                float v0 = fmaxf(acc[mt][nt][0] + bb.x, 0.f);
                float v1 = fmaxf(acc[mt][nt][1] + bb.y, 0.f);
                uint32_t ph, pl;
                split_pack2(v0, v1, ph, pl);
                g_hh[(size_t)r_lo * 128 + kpo] = ph;
                g_hl[(size_t)r_lo * 128 + kpo] = pl;
            }
            if (r_hi < N_NODES) {
                float v0 = fmaxf(acc[mt][nt][2] + bb.x, 0.f);
                float v1 = fmaxf(acc[mt][nt][3] + bb.y, 0.f);
                uint32_t ph, pl;
                split_pack2(v0, v1, ph, pl);
                g_hh[(size_t)r_hi * 128 + kpo] = ph;
                g_hl[(size_t)r_hi * 128 + kpo] = pl;
            }
        }
    }
}

// GEMM2: [p(bf16) | out=q+b2] = h @ [W2_l | W2_r].  K=256, virtual N=256.
__global__ __launch_bounds__(256) void gemm2_kernel(const float* __restrict__ b2,
                                                    float* __restrict__ out) {
    __shared__ SmemGemm sm;
    int tid = threadIdx.x;
    int row0 = blockIdx.x * 128;
    int col0 = blockIdx.y * 64;   // virtual col in [0,256)
    int wid = tid >> 5, lane = tid & 31;
    int g = lane >> 2, tig = lane & 3;
    int wm = (wid & 3) * 32;
    int wn = (wid >> 2) * 32;

    int lrow = tid >> 1;
    int kq = (tid & 1) * 8;
    int arow = row0 + lrow;
    bool rowok = (arow < N_NODES);

    int bn = tid >> 2;
    int kq4 = (tid & 3) * 4;

    float acc[2][4][4];
#pragma unroll
    for (int mt = 0; mt < 2; mt++)
#pragma unroll
        for (int nt = 0; nt < 4; nt++)
#pragma unroll
            for (int i = 0; i < 4; i++) acc[mt][nt][i] = 0.f;

    auto load_stage = [&](int k0, StageRegs& r) {
        int kb = k0 >> 1;
        if (rowok) {
            const uint32_t* srch = &g_hh[(size_t)arow * 128 + kb];
            const uint32_t* srcl = &g_hl[(size_t)arow * 128 + kb];
            r.ah0 = *(const uint4*)(srch + kq);
            r.ah1 = *(const uint4*)(srch + kq + 4);
            r.al0 = *(const uint4*)(srcl + kq);
            r.al1 = *(const uint4*)(srcl + kq + 4);
        } else {
            r.ah0 = r.ah1 = r.al0 = r.al1 = make_uint4(0, 0, 0, 0);
        }
        r.bh = *(const uint4*)&g_W2h[(size_t)(col0 + bn) * 128 + kb + kq4];
        r.bl = *(const uint4*)&g_W2l[(size_t)(col0 + bn) * 128 + kb + kq4];
    };

    StageRegs r;
    load_stage(0, r);
#pragma unroll
    for (int s = 0; s < 8; s++) {
        store_stage(&sm, lrow, kq, bn, kq4, r);
        __syncthreads();
        if (s < 7) load_stage((s + 1) * 32, r);
        compute_chunk(&sm, wm, wn, g, tig, acc);
        __syncthreads();
    }

    // epilogue: col<128 -> bf16 p;  col>=128 -> out = C + b2
#pragma unroll
    for (int nt = 0; nt < 4; nt++) {
        int col = col0 + wn + nt * 8 + tig * 2;   // virtual col
#pragma unroll
        for (int mt = 0; mt < 2; mt++) {
            int r_lo = row0 + wm + mt * 16 + g;
            int r_hi = r_lo + 8;
            if (col < 128) {
                int kpo = col >> 1;
                if (r_lo < N_NODES) {
                    __nv_bfloat162 v = __floats2bfloat162_rn(acc[mt][nt][0], acc[mt][nt][1]);
                    g_pb[(size_t)r_lo * 64 + kpo] = *(uint32_t*)&v;
                }
                if (r_hi < N_NODES) {
                    __nv_bfloat162 v = __floats2bfloat162_rn(acc[mt][nt][2], acc[mt][nt][3]);
                    g_pb[(size_t)r_hi * 64 + kpo] = *(uint32_t*)&v;
                }
            } else {
                int c = col - 128;
                float2 bb = *(const float2*)&b2[c];
                if (r_lo < N_NODES) {
                    float2 v;
                    v.x = acc[mt][nt][0] + bb.x;
                    v.y = acc[mt][nt][1] + bb.y;
                    *(float2*)&out[(size_t)r_lo * 128 + c] = v;
                }
                if (r_hi < N_NODES) {
                    float2 v;
                    v.x = acc[mt][nt][2] + bb.x;
                    v.y = acc[mt][nt][3] + bb.y;
                    *(float2*)&out[(size_t)r_hi * 128 + c] = v;
                }
            }
        }
    }
}

// ---------------- launch ----------------
extern "C" void kernel_launch(void* const* d_in, const int* in_sizes, int n_in,
                              void* d_out, int out_size) {
    const float* x   = (const float*)d_in[0];
    const int*   ei  = (const int*)d_in[1];   // int64 in reference -> int32 in harness
    const float* W1l = (const float*)d_in[2];
    const float* b1  = (const float*)d_in[3];
    const float* W1r = (const float*)d_in[4];
    const float* W2l = (const float*)d_in[5];
    const float* b2  = (const float*)d_in[6];
    const float* W2r = (const float*)d_in[7];
    float* out = (float*)d_out;

    // CSR build: hist (atomics + rank), scan (offsets + deg reset), atomic-free scatter
    hist_kernel<<<(N_E / 4 + 255) / 256, 256>>>(ei);
    scan_kernel<<<1, 1024>>>();
    // fused: atomic-free scatter + split x + split/transposed weights
    scatter_init_kernel<<<(N_NODES * 128 / 4 + 255) / 256, 256>>>(ei, x, W1l, W1r, W2l, W2r);

    // Layer 1
    aggregate_x_kernel<<<(N_NODES + 7) / 8, 256>>>();
    {
        dim3 grid((N_NODES + 127) / 128, 4);
        gemm1_kernel<<<grid, 256>>>(b1);
    }

    // Layer 2
    {
        dim3 grid((N_NODES + 127) / 128, 4);
        gemm2_kernel<<<grid, 256>>>(b2, out);
    }
    aggregate_p_kernel<<<(N_NODES + 7) / 8, 256>>>(out);
}